// round 10
// baseline (speedup 1.0000x reference)
#include <cuda_runtime.h>
#include <cuda_bf16.h>
#include <cuda_fp16.h>
#include <math.h>
#include <stdint.h>

#define BATCH 2
#define SEQ   2048
#define HID   4096
#define NHEAD 32
#define HDIM  128
#define TOKENS (BATCH * SEQ)     // 4096
#define QKVN  (3 * HID)          // 12288
#define HEADS (BATCH * NHEAD)    // 64

typedef __nv_bfloat16 bf16;
typedef __half f16;

// ---------------- scratch (device globals; no allocation allowed) ----------
__device__ float g_qkv[(size_t)TOKENS * QKVN];
__device__ float g_v[(size_t)HEADS * SEQ * HDIM];
__device__ f16   g_hidH[(size_t)TOKENS * HID];
__device__ f16   g_hidL[(size_t)TOKENS * HID];
__device__ f16   g_wqkvt[(size_t)QKVN * HID];
__device__ f16   g_wot[(size_t)HID * HID];
__device__ bf16  g_QH[(size_t)HEADS * SEQ * HDIM];
__device__ bf16  g_QL[(size_t)HEADS * SEQ * HDIM];
__device__ bf16  g_KH[(size_t)HEADS * SEQ * HDIM];
__device__ bf16  g_KL[(size_t)HEADS * SEQ * HDIM];
__device__ bf16  g_VtH[(size_t)HEADS * HDIM * SEQ];
__device__ bf16  g_VtL[(size_t)HEADS * HDIM * SEQ];
__device__ f16   g_attnH[(size_t)TOKENS * HID];
__device__ f16   g_attnL[(size_t)TOKENS * HID];

// ======================= helpers ==================================
__device__ __forceinline__ uint32_t smem_u32_of(const void* p) {
    uint32_t a;
    asm("{ .reg .u64 t; cvta.to.shared.u64 t, %1; cvt.u32.u64 %0, t; }" : "=r"(a) : "l"(p));
    return a;
}
__device__ __forceinline__ void ldm_x4(uint32_t* r, uint32_t addr) {
    asm volatile("ldmatrix.sync.aligned.m8n8.x4.shared.b16 {%0,%1,%2,%3}, [%4];"
                 : "=r"(r[0]), "=r"(r[1]), "=r"(r[2]), "=r"(r[3]) : "r"(addr));
}
__device__ __forceinline__ void mma_bf16(float* d, const uint32_t* a, uint32_t b0, uint32_t b1) {
    asm volatile(
        "mma.sync.aligned.m16n8k16.row.col.f32.bf16.bf16.f32 "
        "{%0,%1,%2,%3},{%4,%5,%6,%7},{%8,%9},{%0,%1,%2,%3};"
        : "+f"(d[0]), "+f"(d[1]), "+f"(d[2]), "+f"(d[3])
        : "r"(a[0]), "r"(a[1]), "r"(a[2]), "r"(a[3]), "r"(b0), "r"(b1));
}
__device__ __forceinline__ void mma_f16(float* d, const uint32_t* a, uint32_t b0, uint32_t b1) {
    asm volatile(
        "mma.sync.aligned.m16n8k16.row.col.f32.f16.f16.f32 "
        "{%0,%1,%2,%3},{%4,%5,%6,%7},{%8,%9},{%0,%1,%2,%3};"
        : "+f"(d[0]), "+f"(d[1]), "+f"(d[2]), "+f"(d[3])
        : "r"(a[0]), "r"(a[1]), "r"(a[2]), "r"(a[3]), "r"(b0), "r"(b1));
}
__device__ __forceinline__ void bfsplit(float x, bf16& hi, bf16& lo) {
    hi = __float2bfloat16_rn(x);
    lo = __float2bfloat16_rn(x - __bfloat162float(hi));
}
__device__ __forceinline__ void hsplit(float x, f16& hi, f16& lo) {
    hi = __float2half_rn(x);
    lo = __float2half_rn(x - __half2float(hi));
}
__device__ __forceinline__ uint32_t pk2(float a, float b) {
    __nv_bfloat162 t = __floats2bfloat162_rn(a, b);
    return *(uint32_t*)&t;
}
__device__ __forceinline__ uint32_t pk2h(float a, float b) {
    __half2 t = __floats2half2_rn(a, b);
    return *(uint32_t*)&t;
}
__device__ __forceinline__ void cp16(uint32_t smem, const void* g) {
    asm volatile("cp.async.cg.shared.global [%0], [%1], 16;" :: "r"(smem), "l"(g) : "memory");
}
__device__ __forceinline__ void cp_commit() {
    asm volatile("cp.async.commit_group;" ::: "memory");
}
template <int N> __device__ __forceinline__ void cp_wait() {
    asm volatile("cp.async.wait_group %0;" :: "n"(N) : "memory");
}

// ============ fp16 2-term compensated tensor-core GEMM ======================
// CTA tile 128(M) x 256(N), KC=64, 512 threads (16 warps: 4M x 4N), 1 CTA/SM.
// smem per stage: Ah 16KB + Al 16KB + Bh 32KB = 64KB; NSTG=2 -> 128KB.
#define KC  64
#define STG_A 16384
#define STG_B 32768
#define STG_BYTES (2 * STG_A + STG_B)   // 65536
#define NSTG 2
#define NTILE 256

__global__ __launch_bounds__(512, 1) void gemm_f16x2(const f16* __restrict__ Ah,
                                                     const f16* __restrict__ Al,
                                                     const f16* __restrict__ Bh,
                                                     float* __restrict__ C,
                                                     int M, int N, int K, int Mtiles)
{
    extern __shared__ char gsm[];
    const uint32_t sbase = smem_u32_of(gsm);

    const int tid = threadIdx.x;
    const int warp = tid >> 5, lane = tid & 31;
    const int wm = warp & 3;          // 4 warps along M (32 rows each)
    const int wn = warp >> 2;         // 4 warps along N (64 cols each)

    // supertile rasterization: groups of 4 N-tiles, M fastest
    const int bx = blockIdx.x;
    const int group = bx / (Mtiles * 4);
    const int rr = bx % (Mtiles * 4);
    const int bm = rr % Mtiles;
    const int bn = group * 4 + rr / Mtiles;

    const f16* Aph = Ah + (size_t)bm * 128 * K;
    const f16* Apl = Al + (size_t)bm * 128 * K;
    const f16* Bph = Bh + (size_t)bn * NTILE * K;

    const int lrow = lane & 15;
    const int lc_half = lane >> 4;

    float acc[2][8][4];
#pragma unroll
    for (int t = 0; t < 2; ++t)
#pragma unroll
        for (int n = 0; n < 8; ++n)
#pragma unroll
            for (int i = 0; i < 4; ++i) acc[t][n][i] = 0.f;

    const int nc = K / KC;   // 64

    auto issue = [&](int c, int st) {
        const int kc = c * KC;
        const uint32_t sb = sbase + st * STG_BYTES;
        // A limbs: 128 rows x 8 chunks = 1024 transfers each
#pragma unroll
        for (int q = 0; q < 2; ++q) {
            const int i = tid + q * 512;
            const int row = i >> 3;
            const int chunk = i & 7;
            const uint32_t doff = (uint32_t)(row * 128 + (chunk ^ (row & 7)) * 16);
            const size_t soff = (size_t)row * K + kc + chunk * 8;
            cp16(sb + doff, Aph + soff);
            cp16(sb + STG_A + doff, Apl + soff);
        }
        // B: 256 rows x 8 chunks = 2048 transfers
#pragma unroll
        for (int q = 0; q < 4; ++q) {
            const int i = tid + q * 512;
            const int row = i >> 3;
            const int chunk = i & 7;
            const uint32_t doff = (uint32_t)(row * 128 + (chunk ^ (row & 7)) * 16);
            const size_t soff = (size_t)row * K + kc + chunk * 8;
            cp16(sb + 2 * STG_A + doff, Bph + soff);
        }
    };

    issue(0, 0); cp_commit();

    for (int c = 0; c < nc; ++c) {
        cp_wait<0>();
        __syncthreads();
        if (c + 1 < nc) { issue(c + 1, (c + 1) & 1); cp_commit(); }

        const int st = c & 1;
        const uint32_t uAh = sbase + st * STG_BYTES;
        const uint32_t uAl = uAh + STG_A;
        const uint32_t uBh = uAh + 2 * STG_A;

#pragma unroll
        for (int ks = 0; ks < 4; ++ks) {
            const int lc = ks * 2 + lc_half;
            uint32_t ah[2][4], al[2][4];
#pragma unroll
            for (int t = 0; t < 2; ++t) {
                const int ar = wm * 32 + t * 16 + lrow;
                const uint32_t aoff = (uint32_t)(ar * 128 + (lc ^ (ar & 7)) * 16);
                ldm_x4(ah[t], uAh + aoff);
                ldm_x4(al[t], uAl + aoff);
            }
#pragma unroll
            for (int nt = 0; nt < 4; ++nt) {
                const int br = wn * 64 + nt * 16 + lrow;
                const uint32_t boff = (uint32_t)(br * 128 + (lc ^ (br & 7)) * 16);
                uint32_t bh[4];
                ldm_x4(bh, uBh + boff);
                mma_f16(acc[0][2 * nt],     ah[0], bh[0], bh[2]);
                mma_f16(acc[1][2 * nt],     ah[1], bh[0], bh[2]);
                mma_f16(acc[0][2 * nt + 1], ah[0], bh[1], bh[3]);
                mma_f16(acc[1][2 * nt + 1], ah[1], bh[1], bh[3]);
                mma_f16(acc[0][2 * nt],     al[0], bh[0], bh[2]);
                mma_f16(acc[1][2 * nt],     al[1], bh[0], bh[2]);
                mma_f16(acc[0][2 * nt + 1], al[0], bh[1], bh[3]);
                mma_f16(acc[1][2 * nt + 1], al[1], bh[1], bh[3]);
            }
        }
    }

    const int g = lane >> 2;
    const int tc2 = (lane & 3) << 1;
#pragma unroll
    for (int t = 0; t < 2; ++t) {
        const int row0 = bm * 128 + wm * 32 + t * 16 + g;
#pragma unroll
        for (int n = 0; n < 8; ++n) {
            const int col = bn * NTILE + wn * 64 + n * 8 + tc2;
            *(float2*)(C + (size_t)row0 * N + col) = make_float2(acc[t][n][0], acc[t][n][1]);
            *(float2*)(C + (size_t)(row0 + 8) * N + col) = make_float2(acc[t][n][2], acc[t][n][3]);
        }
    }
}

// ---------------- elementwise split fp32 -> fp16 hi/lo ----------------------
__global__ __launch_bounds__(256) void split_f32h(const float* __restrict__ in,
                                                  f16* __restrict__ hi,
                                                  f16* __restrict__ lo)
{
    const size_t i4 = (size_t)blockIdx.x * 256 + threadIdx.x;
    float4 v = *(const float4*)(in + i4 * 4);
    f16 h[4], l[4];
    hsplit(v.x, h[0], l[0]); hsplit(v.y, h[1], l[1]);
    hsplit(v.z, h[2], l[2]); hsplit(v.w, h[3], l[3]);
    *(uint2*)(hi + i4 * 4) = *(uint2*)h;
    *(uint2*)(lo + i4 * 4) = *(uint2*)l;
}

// ---------------- transpose + round to single fp16 --------------------------
__global__ __launch_bounds__(256) void transpose_f16(const float* __restrict__ in,
                                                     f16* __restrict__ out,
                                                     int R, int Cc)
{
    __shared__ float t[32][33];
    const int c = blockIdx.x * 32 + threadIdx.x;
    const int r0 = blockIdx.y * 32 + threadIdx.y;
#pragma unroll
    for (int i = 0; i < 4; ++i)
        t[threadIdx.y + i * 8][threadIdx.x] = in[(size_t)(r0 + i * 8) * Cc + c];
    __syncthreads();
    const int rc = blockIdx.y * 32 + threadIdx.x;
    const int c0 = blockIdx.x * 32 + threadIdx.y;
#pragma unroll
    for (int i = 0; i < 4; ++i)
        out[(size_t)(c0 + i * 8) * R + rc] = __float2half_rn(t[threadIdx.x][threadIdx.y + i * 8]);
}

// ---------------- V transpose + split (bf16, attention path) ----------------
__global__ __launch_bounds__(256) void vt_split(const float* __restrict__ Vg,
                                                bf16* __restrict__ VtH,
                                                bf16* __restrict__ VtL)
{
    __shared__ float t[32][33];
    const int bh = blockIdx.z;
    const float* in = Vg + (size_t)bh * SEQ * HDIM;
    const int s0 = blockIdx.x * 32;
    const int d0 = blockIdx.y * 32;
#pragma unroll
    for (int i = 0; i < 4; ++i)
        t[threadIdx.y + i * 8][threadIdx.x] = in[(size_t)(s0 + threadIdx.y + i * 8) * HDIM + d0 + threadIdx.x];
    __syncthreads();
    bf16* oh = VtH + (size_t)bh * HDIM * SEQ;
    bf16* ol = VtL + (size_t)bh * HDIM * SEQ;
#pragma unroll
    for (int i = 0; i < 4; ++i) {
        float v = t[threadIdx.x][threadIdx.y + i * 8];
        bf16 h, l;
        bfsplit(v, h, l);
        oh[(size_t)(d0 + threadIdx.y + i * 8) * SEQ + s0 + threadIdx.x] = h;
        ol[(size_t)(d0 + threadIdx.y + i * 8) * SEQ + s0 + threadIdx.x] = l;
    }
}

// ---------------- RoPE (NeoX) + split (bf16, attention path) ----------------
__global__ __launch_bounds__(128) void rope_split2(const float* __restrict__ qkv,
                                                   const int* __restrict__ pos_ids,
                                                   bf16* __restrict__ QH, bf16* __restrict__ QL,
                                                   bf16* __restrict__ KH, bf16* __restrict__ KL,
                                                   float* __restrict__ Vh)
{
    const int token = blockIdx.x;
    const int b = token / SEQ;
    const int s = token % SEQ;
    __shared__ float cs[64], sn[64];
    const int tid = threadIdx.x;
    if (tid < 64) {
        double inv = exp(-9.210340371976184 * ((double)(2 * tid) / 128.0));
        double ang = (double)pos_ids[token] * inv;
        cs[tid] = (float)cos(ang);
        sn[tid] = (float)sin(ang);
    }
    __syncthreads();
    const float* base = qkv + (size_t)token * QKVN;

    for (int p = tid; p < NHEAD * 64; p += 128) {
        int h = p >> 6;
        int i = p & 63;
        float c = cs[i], sv = sn[i];
        size_t ob = ((size_t)(b * NHEAD + h) * SEQ + s) * HDIM;
        float q1 = base[h * HDIM + i];
        float q2 = base[h * HDIM + 64 + i];
        float r1 = q1 * c - q2 * sv;
        float r2 = q2 * c + q1 * sv;
        bf16 hh, ll;
        bfsplit(r1, hh, ll); QH[ob + i] = hh;      QL[ob + i] = ll;
        bfsplit(r2, hh, ll); QH[ob + 64 + i] = hh; QL[ob + 64 + i] = ll;
        float k1 = base[HID + h * HDIM + i];
        float k2 = base[HID + h * HDIM + 64 + i];
        r1 = k1 * c - k2 * sv;
        r2 = k2 * c + k1 * sv;
        bfsplit(r1, hh, ll); KH[ob + i] = hh;      KL[ob + i] = ll;
        bfsplit(r2, hh, ll); KH[ob + 64 + i] = hh; KL[ob + 64 + i] = ll;
    }
    for (int p = tid; p < HID; p += 128) {
        int h = p >> 7;
        int d = p & 127;
        Vh[((size_t)(b * NHEAD + h) * SEQ + s) * HDIM + d] = base[2 * HID + p];
    }
}

// ---------------- tensor-core flash attention (causal, bf16x3) --------------
#define QSTR 136
#define VSTR 72
#define oQH 0
#define oQL (oQH + 128 * QSTR * 2)
#define oKH (oQL + 128 * QSTR * 2)
#define oKL (oKH + 2 * 64 * QSTR * 2)
#define oVH (oKL + 2 * 64 * QSTR * 2)
#define oVL (oVH + 2 * 128 * VSTR * 2)
#define ATT_SMEM (oVL + 2 * 128 * VSTR * 2)

__global__ __launch_bounds__(256, 1) void flash_mma(const bf16* __restrict__ QHg,
                                                    const bf16* __restrict__ QLg,
                                                    const bf16* __restrict__ KHg,
                                                    const bf16* __restrict__ KLg,
                                                    const bf16* __restrict__ VtHg,
                                                    const bf16* __restrict__ VtLg,
                                                    f16* __restrict__ attnH,
                                                    f16* __restrict__ attnL)
{
    extern __shared__ char asm_buf[];
    const uint32_t sb = smem_u32_of(asm_buf);

    const int tid = threadIdx.x;
    const int warp = tid >> 5, lane = tid & 31;
    const int g = lane >> 2;
    const int lam = lane & 3;
    const int lrow = lane & 15;
    const int lkh = (lane >> 4) << 3;

    const int qt = (int)(gridDim.x - 1 - blockIdx.x);
    const int h = blockIdx.y;
    const int b = blockIdx.z;
    const int qb = qt * 128;
    const size_t hoff = (size_t)(b * NHEAD + h) * SEQ * HDIM;
    const size_t voff = (size_t)(b * NHEAD + h) * HDIM * SEQ;

#pragma unroll
    for (int j = 0; j < 8; ++j) {
        const int i = tid + j * 256;
        const int row = i >> 4;
        const int seg = (i & 15) << 3;
        const uint32_t doff = (uint32_t)(row * QSTR + seg) * 2;
        const size_t soff = hoff + (size_t)(qb + row) * HDIM + seg;
        cp16(sb + oQH + doff, QHg + soff);
        cp16(sb + oQL + doff, QLg + soff);
    }
    cp_commit();

    const int ktmax = 2 * qt + 1;

    auto issueKV = [&](int kt, int buf) {
        const int kb = kt * 64;
#pragma unroll
        for (int j = 0; j < 4; ++j) {
            const int i = tid + j * 256;
            const int krow = i >> 4;
            const int kseg = (i & 15) << 3;
            const uint32_t kdoff = (uint32_t)(krow * QSTR + kseg) * 2;
            const size_t ksoff = hoff + (size_t)(kb + krow) * HDIM + kseg;
            cp16(sb + oKH + buf * (64 * QSTR * 2) + kdoff, KHg + ksoff);
            cp16(sb + oKL + buf * (64 * QSTR * 2) + kdoff, KLg + ksoff);
            const int vrow = i >> 3;
            const int vseg = (i & 7) << 3;
            const uint32_t vdoff = (uint32_t)(vrow * VSTR + vseg) * 2;
            const size_t vsoff = voff + (size_t)vrow * SEQ + kb + vseg;
            cp16(sb + oVH + buf * (128 * VSTR * 2) + vdoff, VtHg + vsoff);
            cp16(sb + oVL + buf * (128 * VSTR * 2) + vdoff, VtLg + vsoff);
        }
    };

    issueKV(0, 0);
    cp_commit();

    float oacc[16][4];
#pragma unroll
    for (int n = 0; n < 16; ++n)
#pragma unroll
        for (int i = 0; i < 4; ++i) oacc[n][i] = 0.f;
    float m0 = -1e30f, m1 = -1e30f, l0 = 0.f, l1 = 0.f;
    const float scale2 = 0.1275174324f;   // (1/sqrt(128)) * log2(e)

    const int r0g = qb + warp * 16 + g;
    const int r1g = r0g + 8;

    for (int kt = 0; kt <= ktmax; ++kt) {
        const int kb = kt * 64;
        const int buf = kt & 1;

        cp_wait<0>();
        __syncthreads();
        if (kt < ktmax) { issueKV(kt + 1, buf ^ 1); cp_commit(); }

        const uint32_t uQH = sb + oQH, uQL = sb + oQL;
        const uint32_t uKH = sb + oKH + buf * (64 * QSTR * 2);
        const uint32_t uKL = sb + oKL + buf * (64 * QSTR * 2);
        const uint32_t uVH = sb + oVH + buf * (128 * VSTR * 2);
        const uint32_t uVL = sb + oVL + buf * (128 * VSTR * 2);

        float sacc[8][4];
#pragma unroll
        for (int n = 0; n < 8; ++n)
#pragma unroll
            for (int i = 0; i < 4; ++i) sacc[n][i] = 0.f;

#pragma unroll
        for (int ks = 0; ks < 8; ++ks) {
            uint32_t ah[4], al[4];
            const uint32_t aoff = (uint32_t)(((warp * 16 + lrow) * QSTR + ks * 16 + lkh) * 2);
            ldm_x4(ah, uQH + aoff);
            ldm_x4(al, uQL + aoff);
#pragma unroll
            for (int ntp = 0; ntp < 2; ++ntp) {
                const int nt0 = 2 * ntp, nt1 = 2 * ntp + 1;
                uint32_t bh0[4], bl0[4], bh1[4], bl1[4];
                const uint32_t b0off = (uint32_t)(((nt0 * 16 + lrow) * QSTR + ks * 16 + lkh) * 2);
                const uint32_t b1off = (uint32_t)(((nt1 * 16 + lrow) * QSTR + ks * 16 + lkh) * 2);
                ldm_x4(bh0, uKH + b0off);
                ldm_x4(bl0, uKL + b0off);
                ldm_x4(bh1, uKH + b1off);
                ldm_x4(bl1, uKL + b1off);
                mma_bf16(sacc[2 * nt0],     ah, bh0[0], bh0[2]);
                mma_bf16(sacc[2 * nt0 + 1], ah, bh0[1], bh0[3]);
                mma_bf16(sacc[2 * nt1],     ah, bh1[0], bh1[2]);
                mma_bf16(sacc[2 * nt1 + 1], ah, bh1[1], bh1[3]);
                mma_bf16(sacc[2 * nt0],     ah, bl0[0], bl0[2]);
                mma_bf16(sacc[2 * nt0 + 1], ah, bl0[1], bl0[3]);
                mma_bf16(sacc[2 * nt1],     ah, bl1[0], bl1[2]);
                mma_bf16(sacc[2 * nt1 + 1], ah, bl1[1], bl1[3]);
                mma_bf16(sacc[2 * nt0],     al, bh0[0], bh0[2]);
                mma_bf16(sacc[2 * nt0 + 1], al, bh0[1], bh0[3]);
                mma_bf16(sacc[2 * nt1],     al, bh1[0], bh1[2]);
                mma_bf16(sacc[2 * nt1 + 1], al, bh1[1], bh1[3]);
            }
        }

        const bool need_mask = (kt >= 2 * qt);
        float rm0 = -1e30f, rm1 = -1e30f;
#pragma unroll
        for (int j = 0; j < 8; ++j) {
            const int cg0 = kb + j * 8 + 2 * lam;
#pragma unroll
            for (int i = 0; i < 4; ++i) {
                float v = sacc[j][i] * scale2;
                if (need_mask) {
                    const int cg = cg0 + (i & 1);
                    const int rg = (i < 2) ? r0g : r1g;
                    if (cg > rg) v = -1e30f;
                }
                sacc[j][i] = v;
            }
            rm0 = fmaxf(rm0, fmaxf(sacc[j][0], sacc[j][1]));
            rm1 = fmaxf(rm1, fmaxf(sacc[j][2], sacc[j][3]));
        }
#pragma unroll
        for (int off = 1; off <= 2; off <<= 1) {
            rm0 = fmaxf(rm0, __shfl_xor_sync(0xffffffffu, rm0, off));
            rm1 = fmaxf(rm1, __shfl_xor_sync(0xffffffffu, rm1, off));
        }
        const float mn0 = fmaxf(m0, rm0);
        const float mn1 = fmaxf(m1, rm1);
        const float al0 = exp2f(m0 - mn0);
        const float al1 = exp2f(m1 - mn1);
        m0 = mn0; m1 = mn1;

        float rs0 = 0.f, rs1 = 0.f;
#pragma unroll
        for (int j = 0; j < 8; ++j) {
            sacc[j][0] = exp2f(sacc[j][0] - mn0);
            sacc[j][1] = exp2f(sacc[j][1] - mn0);
            sacc[j][2] = exp2f(sacc[j][2] - mn1);
            sacc[j][3] = exp2f(sacc[j][3] - mn1);
            rs0 += sacc[j][0] + sacc[j][1];
            rs1 += sacc[j][2] + sacc[j][3];
        }
#pragma unroll
        for (int off = 1; off <= 2; off <<= 1) {
            rs0 += __shfl_xor_sync(0xffffffffu, rs0, off);
            rs1 += __shfl_xor_sync(0xffffffffu, rs1, off);
        }
        l0 = l0 * al0 + rs0;
        l1 = l1 * al1 + rs1;

#pragma unroll
        for (int n = 0; n < 16; ++n) {
            oacc[n][0] *= al0; oacc[n][1] *= al0;
            oacc[n][2] *= al1; oacc[n][3] *= al1;
        }

        uint32_t pah[4][4], pal[4][4];
#pragma unroll
        for (int j2 = 0; j2 < 4; ++j2) {
            float p00 = sacc[2 * j2][0],     p01 = sacc[2 * j2][1];
            float p02 = sacc[2 * j2][2],     p03 = sacc[2 * j2][3];
            float p10 = sacc[2 * j2 + 1][0], p11 = sacc[2 * j2 + 1][1];
            float p12 = sacc[2 * j2 + 1][2], p13 = sacc[2 * j2 + 1][3];
            pah[j2][0] = pk2(p00, p01);
            pah[j2][1] = pk2(p02, p03);
            pah[j2][2] = pk2(p10, p11);
            pah[j2][3] = pk2(p12, p13);
            bf16 hh;
            hh = __float2bfloat16_rn(p00); p00 -= __bfloat162float(hh);
            hh = __float2bfloat16_rn(p01); p01 -= __bfloat162float(hh);
            hh = __float2bfloat16_rn(p02); p02 -= __bfloat162float(hh);
            hh = __float2bfloat16_rn(p03); p03 -= __bfloat162float(hh);
            hh = __float2bfloat16_rn(p10); p10 -= __bfloat162float(hh);
            hh = __float2bfloat16_rn(p11); p11 -= __bfloat162float(hh);
            hh = __float2bfloat16_rn(p12); p12 -= __bfloat162float(hh);
            hh = __float2bfloat16_rn(p13); p13 -= __bfloat162float(hh);
            pal[j2][0] = pk2(p00, p01);
            pal[j2][1] = pk2(p02, p03);
            pal[j2][2] = pk2(p10, p11);
            pal[j2][3] = pk2(p12, p13);
        }

#pragma unroll
        for (int ntp = 0; ntp < 4; ++ntp) {
            const int nt0 = 2 * ntp, nt1 = 2 * ntp + 1;
#pragma unroll
            for (int j2 = 0; j2 < 4; ++j2) {
                uint32_t vh0[4], vl0[4], vh1[4], vl1[4];
                const uint32_t v0off = (uint32_t)(((nt0 * 16 + lrow) * VSTR + j2 * 16 + lkh) * 2);
                const uint32_t v1off = (uint32_t)(((nt1 * 16 + lrow) * VSTR + j2 * 16 + lkh) * 2);
                ldm_x4(vh0, uVH + v0off);
                ldm_x4(vl0, uVL + v0off);
                ldm_x4(vh1, uVH + v1off);
                ldm_x4(vl1, uVL + v1off);
                mma_bf16(oacc[2 * nt0],     pah[j2], vh0[0], vh0[2]);
                mma_bf16(oacc[2 * nt0 + 1], pah[j2], vh0[1], vh0[3]);
                mma_bf16(oacc[2 * nt1],     pah[j2], vh1[0], vh1[2]);
                mma_bf16(oacc[2 * nt1 + 1], pah[j2], vh1[1], vh1[3]);
                mma_bf16(oacc[2 * nt0],     pah[j2], vl0[0], vl0[2]);
                mma_bf16(oacc[2 * nt0 + 1], pah[j2], vl0[1], vl0[3]);
                mma_bf16(oacc[2 * nt1],     pah[j2], vl1[0], vl1[2]);
                mma_bf16(oacc[2 * nt1 + 1], pah[j2], vl1[1], vl1[3]);
                mma_bf16(oacc[2 * nt0],     pal[j2], vh0[0], vh0[2]);
                mma_bf16(oacc[2 * nt0 + 1], pal[j2], vh0[1], vh0[3]);
                mma_bf16(oacc[2 * nt1],     pal[j2], vh1[0], vh1[2]);
                mma_bf16(oacc[2 * nt1 + 1], pal[j2], vh1[1], vh1[3]);
            }
        }
    }

    // epilogue: normalize, split to fp16 hi/lo for the O-proj
    const float i0 = 1.0f / l0;
    const float i1 = 1.0f / l1;
    const size_t row0 = ((size_t)b * SEQ + r0g) * HID + h * HDIM;
    const size_t row1 = ((size_t)b * SEQ + r1g) * HID + h * HDIM;
#pragma unroll
    for (int n = 0; n < 16; ++n) {
        const int col = n * 8 + 2 * lam;
        float x0 = oacc[n][0] * i0, x1 = oacc[n][1] * i0;
        float y0 = oacc[n][2] * i1, y1 = oacc[n][3] * i1;
        *(uint32_t*)(attnH + row0 + col) = pk2h(x0, x1);
        *(uint32_t*)(attnH + row1 + col) = pk2h(y0, y1);
        f16 hb;
        hb = __float2half_rn(x0); x0 -= __half2float(hb);
        hb = __float2half_rn(x1); x1 -= __half2float(hb);
        hb = __float2half_rn(y0); y0 -= __half2float(hb);
        hb = __float2half_rn(y1); y1 -= __half2float(hb);
        *(uint32_t*)(attnL + row0 + col) = pk2h(x0, x1);
        *(uint32_t*)(attnL + row1 + col) = pk2h(y0, y1);
    }
}

// ---------------------------------------------------------------------------
extern "C" void kernel_launch(void* const* d_in, const int* in_sizes, int n_in,
                              void* d_out, int out_size)
{
    (void)in_sizes; (void)n_in; (void)out_size;
    const float* hidden = (const float*)d_in[0];
    const float* w_qkv  = (const float*)d_in[1];
    const float* w_o    = (const float*)d_in[2];
    const int*   pos    = (const int*)d_in[3];
    float* out = (float*)d_out;

    float *qkv, *v;
    f16 *hidH, *hidL, *wqkvt, *wot, *attnH, *attnL;
    bf16 *QH, *QL, *KH, *KL, *VtH, *VtL;
    cudaGetSymbolAddress((void**)&qkv,   g_qkv);
    cudaGetSymbolAddress((void**)&v,     g_v);
    cudaGetSymbolAddress((void**)&hidH,  g_hidH);
    cudaGetSymbolAddress((void**)&hidL,  g_hidL);
    cudaGetSymbolAddress((void**)&wqkvt, g_wqkvt);
    cudaGetSymbolAddress((void**)&wot,   g_wot);
    cudaGetSymbolAddress((void**)&QH,    g_QH);
    cudaGetSymbolAddress((void**)&QL,    g_QL);
    cudaGetSymbolAddress((void**)&KH,    g_KH);
    cudaGetSymbolAddress((void**)&KL,    g_KL);
    cudaGetSymbolAddress((void**)&VtH,   g_VtH);
    cudaGetSymbolAddress((void**)&VtL,   g_VtL);
    cudaGetSymbolAddress((void**)&attnH, g_attnH);
    cudaGetSymbolAddress((void**)&attnL, g_attnL);

    // 0) pre-split activations (fp16 hi/lo) + transpose weights (single fp16)
    split_f32h<<<(TOKENS * HID) / 1024, 256>>>(hidden, hidH, hidL);
    transpose_f16<<<dim3(QKVN / 32, HID / 32), dim3(32, 8)>>>(w_qkv, wqkvt, HID, QKVN);
    transpose_f16<<<dim3(HID / 32, HID / 32), dim3(32, 8)>>>(w_o, wot, HID, HID);

    const int gsmem = NSTG * STG_BYTES;   // 131072 -> 1 CTA/SM, 512 threads
    cudaFuncSetAttribute(gemm_f16x2, cudaFuncAttributeMaxDynamicSharedMemorySize, gsmem);

    // 1) QKV projection (fp16 2-term), tile 128x256
    gemm_f16x2<<<(TOKENS / 128) * (QKVN / NTILE), 512, gsmem>>>(
        hidH, hidL, wqkvt, qkv, TOKENS, QKVN, HID, TOKENS / 128);

    // 2) RoPE + split to head-major bf16; V fp32 head-major
    rope_split2<<<TOKENS, 128>>>(qkv, pos, QH, QL, KH, KL, v);

    // 3) V transpose + split per head
    vt_split<<<dim3(SEQ / 32, HDIM / 32, HEADS), dim3(32, 8)>>>(v, VtH, VtL);

    // 4) tensor-core causal flash attention -> fp16-split attn
    cudaFuncSetAttribute(flash_mma, cudaFuncAttributeMaxDynamicSharedMemorySize, ATT_SMEM);
    flash_mma<<<dim3(SEQ / 128, NHEAD, BATCH), 256, ATT_SMEM>>>(
        QH, QL, KH, KL, VtH, VtL, attnH, attnL);

    // 5) output projection (fp16 2-term), tile 128x256
    gemm_f16x2<<<(TOKENS / 128) * (HID / NTILE), 512, gsmem>>>(
        attnH, attnL, wot, out, TOKENS, HID, HID, TOKENS / 128);
}

// round 11
// speedup vs baseline: 1.1015x; 1.1015x over previous
#include <cuda_runtime.h>
#include <cuda_bf16.h>
#include <cuda_fp16.h>
#include <math.h>
#include <stdint.h>

#define BATCH 2
#define SEQ   2048
#define HID   4096
#define NHEAD 32
#define HDIM  128
#define TOKENS (BATCH * SEQ)     // 4096
#define QKVN  (3 * HID)          // 12288
#define HEADS (BATCH * NHEAD)    // 64

typedef __nv_bfloat16 bf16;
typedef __half f16;

// ---------------- scratch (device globals; no allocation allowed) ----------
__device__ f16   g_hidH[(size_t)TOKENS * HID];
__device__ f16   g_hidL[(size_t)TOKENS * HID];
__device__ f16   g_wqkvt[(size_t)QKVN * HID];
__device__ f16   g_wot[(size_t)HID * HID];
__device__ float g_ctab[(size_t)TOKENS * 64];
__device__ float g_stab[(size_t)TOKENS * 64];
__device__ bf16  g_QH[(size_t)HEADS * SEQ * HDIM];
__device__ bf16  g_QL[(size_t)HEADS * SEQ * HDIM];
__device__ bf16  g_KH[(size_t)HEADS * SEQ * HDIM];
__device__ bf16  g_KL[(size_t)HEADS * SEQ * HDIM];
__device__ bf16  g_VtH[(size_t)HEADS * HDIM * SEQ];
__device__ bf16  g_VtL[(size_t)HEADS * HDIM * SEQ];
__device__ f16   g_attnH[(size_t)TOKENS * HID];
__device__ f16   g_attnL[(size_t)TOKENS * HID];

// ======================= helpers ==================================
__device__ __forceinline__ uint32_t smem_u32_of(const void* p) {
    uint32_t a;
    asm("{ .reg .u64 t; cvta.to.shared.u64 t, %1; cvt.u32.u64 %0, t; }" : "=r"(a) : "l"(p));
    return a;
}
__device__ __forceinline__ void ldm_x4(uint32_t* r, uint32_t addr) {
    asm volatile("ldmatrix.sync.aligned.m8n8.x4.shared.b16 {%0,%1,%2,%3}, [%4];"
                 : "=r"(r[0]), "=r"(r[1]), "=r"(r[2]), "=r"(r[3]) : "r"(addr));
}
__device__ __forceinline__ void mma_bf16(float* d, const uint32_t* a, uint32_t b0, uint32_t b1) {
    asm volatile(
        "mma.sync.aligned.m16n8k16.row.col.f32.bf16.bf16.f32 "
        "{%0,%1,%2,%3},{%4,%5,%6,%7},{%8,%9},{%0,%1,%2,%3};"
        : "+f"(d[0]), "+f"(d[1]), "+f"(d[2]), "+f"(d[3])
        : "r"(a[0]), "r"(a[1]), "r"(a[2]), "r"(a[3]), "r"(b0), "r"(b1));
}
__device__ __forceinline__ void mma_f16(float* d, const uint32_t* a, uint32_t b0, uint32_t b1) {
    asm volatile(
        "mma.sync.aligned.m16n8k16.row.col.f32.f16.f16.f32 "
        "{%0,%1,%2,%3},{%4,%5,%6,%7},{%8,%9},{%0,%1,%2,%3};"
        : "+f"(d[0]), "+f"(d[1]), "+f"(d[2]), "+f"(d[3])
        : "r"(a[0]), "r"(a[1]), "r"(a[2]), "r"(a[3]), "r"(b0), "r"(b1));
}
__device__ __forceinline__ void bfsplit(float x, bf16& hi, bf16& lo) {
    hi = __float2bfloat16_rn(x);
    lo = __float2bfloat16_rn(x - __bfloat162float(hi));
}
__device__ __forceinline__ void hsplit(float x, f16& hi, f16& lo) {
    hi = __float2half_rn(x);
    lo = __float2half_rn(x - __half2float(hi));
}
__device__ __forceinline__ uint32_t pk2(float a, float b) {
    __nv_bfloat162 t = __floats2bfloat162_rn(a, b);
    return *(uint32_t*)&t;
}
__device__ __forceinline__ uint32_t pk2h(float a, float b) {
    __half2 t = __floats2half2_rn(a, b);
    return *(uint32_t*)&t;
}
__device__ __forceinline__ void cp16(uint32_t smem, const void* g) {
    asm volatile("cp.async.cg.shared.global [%0], [%1], 16;" :: "r"(smem), "l"(g) : "memory");
}
__device__ __forceinline__ void cp_commit() {
    asm volatile("cp.async.commit_group;" ::: "memory");
}
template <int N> __device__ __forceinline__ void cp_wait() {
    asm volatile("cp.async.wait_group %0;" :: "n"(N) : "memory");
}

// ============ fp16 2-term compensated tensor-core GEMM ======================
// R9 config: tile 128x128, KC=64, 256 threads, NSTG=2, 2 CTAs/SM.
// mode 0: write fp32 C.   mode 1: fused QKV epilogue (RoPE Q/K, transpose V).
#define KC  64
#define STG_ARR (128 * KC * 2)       // 16384 B per array per stage
#define STG_BYTES (3 * STG_ARR)      // 49152 B (Ah, Al, Bh)
#define NSTG 2
#define EPAD 129                      // fp32 epilogue smem stride

__global__ __launch_bounds__(256, 2) void gemm_f16x2(const f16* __restrict__ Ah,
                                                     const f16* __restrict__ Al,
                                                     const f16* __restrict__ Bh,
                                                     float* __restrict__ C,
                                                     const float* __restrict__ ctab,
                                                     const float* __restrict__ stab,
                                                     bf16* __restrict__ QH, bf16* __restrict__ QL,
                                                     bf16* __restrict__ KH, bf16* __restrict__ KL,
                                                     bf16* __restrict__ VtH, bf16* __restrict__ VtL,
                                                     int M, int N, int K, int Mtiles, int mode)
{
    extern __shared__ char gsm[];
    const uint32_t sbase = smem_u32_of(gsm);

    const int tid = threadIdx.x;
    const int warp = tid >> 5, lane = tid & 31;
    const int wm = warp & 3;
    const int wn = warp >> 2;

    const int bx = blockIdx.x;
    const int group = bx / (Mtiles * 8);
    const int rr = bx % (Mtiles * 8);
    const int bm = rr % Mtiles;
    const int bn = group * 8 + rr / Mtiles;

    const f16* Aph = Ah + (size_t)bm * 128 * K;
    const f16* Apl = Al + (size_t)bm * 128 * K;
    const f16* Bph = Bh + (size_t)bn * 128 * K;

    const int lrow = lane & 15;
    const int lc_half = lane >> 4;

    float acc[2][8][4];
#pragma unroll
    for (int t = 0; t < 2; ++t)
#pragma unroll
        for (int n = 0; n < 8; ++n)
#pragma unroll
            for (int i = 0; i < 4; ++i) acc[t][n][i] = 0.f;

    const int nc = K / KC;   // 64

    auto issue = [&](int c, int st) {
        const int kc = c * KC;
        const uint32_t sb = sbase + st * STG_BYTES;
#pragma unroll
        for (int q = 0; q < 4; ++q) {
            const int i = tid + q * 256;
            const int row = i >> 3;
            const int chunk = i & 7;
            const int pchunk = chunk ^ (row & 7);
            const uint32_t doff = (uint32_t)(row * 128 + pchunk * 16);
            const size_t soff = (size_t)row * K + kc + chunk * 8;
            cp16(sb + 0 * STG_ARR + doff, Aph + soff);
            cp16(sb + 1 * STG_ARR + doff, Apl + soff);
            cp16(sb + 2 * STG_ARR + doff, Bph + soff);
        }
    };

    issue(0, 0); cp_commit();

    for (int c = 0; c < nc; ++c) {
        cp_wait<0>();
        __syncthreads();
        if (c + 1 < nc) { issue(c + 1, (c + 1) & 1); cp_commit(); }

        const int st = c & 1;
        const uint32_t uAh = sbase + st * STG_BYTES;
        const uint32_t uAl = uAh + STG_ARR;
        const uint32_t uBh = uAh + 2 * STG_ARR;

#pragma unroll
        for (int ks = 0; ks < 4; ++ks) {
            const int lc = ks * 2 + lc_half;
            uint32_t ah[2][4], al[2][4];
#pragma unroll
            for (int t = 0; t < 2; ++t) {
                const int ar = wm * 32 + t * 16 + lrow;
                const uint32_t aoff = (uint32_t)(ar * 128 + (lc ^ (ar & 7)) * 16);
                ldm_x4(ah[t], uAh + aoff);
                ldm_x4(al[t], uAl + aoff);
            }
#pragma unroll
            for (int nt = 0; nt < 4; ++nt) {
                const int br = wn * 64 + nt * 16 + lrow;
                const uint32_t boff = (uint32_t)(br * 128 + (lc ^ (br & 7)) * 16);
                uint32_t bh[4];
                ldm_x4(bh, uBh + boff);
                mma_f16(acc[0][2 * nt],     ah[0], bh[0], bh[2]);
                mma_f16(acc[1][2 * nt],     ah[1], bh[0], bh[2]);
                mma_f16(acc[0][2 * nt + 1], ah[0], bh[1], bh[3]);
                mma_f16(acc[1][2 * nt + 1], ah[1], bh[1], bh[3]);
                mma_f16(acc[0][2 * nt],     al[0], bh[0], bh[2]);
                mma_f16(acc[1][2 * nt],     al[1], bh[0], bh[2]);
                mma_f16(acc[0][2 * nt + 1], al[0], bh[1], bh[3]);
                mma_f16(acc[1][2 * nt + 1], al[1], bh[1], bh[3]);
            }
        }
    }

    const int g = lane >> 2;
    const int tc2 = (lane & 3) << 1;

    if (mode == 0) {
        // plain fp32 output
#pragma unroll
        for (int t = 0; t < 2; ++t) {
            const int row0 = bm * 128 + wm * 32 + t * 16 + g;
#pragma unroll
            for (int n = 0; n < 8; ++n) {
                const int col = bn * 128 + wn * 64 + n * 8 + tc2;
                *(float2*)(C + (size_t)row0 * N + col) = make_float2(acc[t][n][0], acc[t][n][1]);
                *(float2*)(C + (size_t)(row0 + 8) * N + col) = make_float2(acc[t][n][2], acc[t][n][3]);
            }
        }
        return;
    }

    // -------- fused QKV epilogue: stage tile in smem (stride EPAD) ----------
    float* spad = (float*)gsm;
    __syncthreads();   // all warps done with pipeline buffers
#pragma unroll
    for (int t = 0; t < 2; ++t) {
        const int r0 = wm * 32 + t * 16 + g;
#pragma unroll
        for (int n = 0; n < 8; ++n) {
            const int col = wn * 64 + n * 8 + tc2;
            spad[r0 * EPAD + col]           = acc[t][n][0];
            spad[r0 * EPAD + col + 1]       = acc[t][n][1];
            spad[(r0 + 8) * EPAD + col]     = acc[t][n][2];
            spad[(r0 + 8) * EPAD + col + 1] = acc[t][n][3];
        }
    }
    __syncthreads();

    const int region = bn >> 5;      // 0:Q 1:K 2:V   (96 N-tiles, 32 per region)
    const int head = bn & 31;

    if (region < 2) {
        bf16* OH = region ? KH : QH;
        bf16* OL = region ? KL : QL;
#pragma unroll
        for (int q = 0; q < 32; ++q) {
            const int p = tid + q * 256;         // 0..8191
            const int tok = p >> 6;
            const int i = p & 63;
            const int gtok = bm * 128 + tok;
            const float x1 = spad[tok * EPAD + i];
            const float x2 = spad[tok * EPAD + 64 + i];
            const float cv = ctab[(size_t)gtok * 64 + i];
            const float sv = stab[(size_t)gtok * 64 + i];
            const float r1 = x1 * cv - x2 * sv;
            const float r2 = x2 * cv + x1 * sv;
            const int bb = gtok >> 11;           // /SEQ
            const int ss = gtok & 2047;
            const size_t ob = ((size_t)(bb * NHEAD + head) * SEQ + ss) * HDIM;
            bf16 hh, ll;
            bfsplit(r1, hh, ll); OH[ob + i] = hh;      OL[ob + i] = ll;
            bfsplit(r2, hh, ll); OH[ob + 64 + i] = hh; OL[ob + 64 + i] = ll;
        }
    } else {
#pragma unroll
        for (int q = 0; q < 64; ++q) {
            const int p = tid + q * 256;         // 0..16383
            const int tok = p & 127;
            const int d = p >> 7;
            const int gtok = bm * 128 + tok;
            const float v = spad[tok * EPAD + d];
            const int bb = gtok >> 11;
            const int ss = gtok & 2047;
            const size_t od = ((size_t)(bb * NHEAD + head) * HDIM + d) * SEQ + ss;
            bf16 hh, ll;
            bfsplit(v, hh, ll);
            VtH[od] = hh;
            VtL[od] = ll;
        }
    }
}

// ---------------- RoPE cos/sin table (double-accuracy, one pass) ------------
__global__ __launch_bounds__(64) void rope_tab(const int* __restrict__ pos,
                                               float* __restrict__ ct,
                                               float* __restrict__ st)
{
    const int tok = blockIdx.x;
    const int i = threadIdx.x;
    double inv = exp(-9.210340371976184 * ((double)(2 * i) / 128.0));
    double ang = (double)pos[tok] * inv;
    ct[(size_t)tok * 64 + i] = (float)cos(ang);
    st[(size_t)tok * 64 + i] = (float)sin(ang);
}

// ---------------- elementwise split fp32 -> fp16 hi/lo ----------------------
__global__ __launch_bounds__(256) void split_f32h(const float* __restrict__ in,
                                                  f16* __restrict__ hi,
                                                  f16* __restrict__ lo)
{
    const size_t i4 = (size_t)blockIdx.x * 256 + threadIdx.x;
    float4 v = *(const float4*)(in + i4 * 4);
    f16 h[4], l[4];
    hsplit(v.x, h[0], l[0]); hsplit(v.y, h[1], l[1]);
    hsplit(v.z, h[2], l[2]); hsplit(v.w, h[3], l[3]);
    *(uint2*)(hi + i4 * 4) = *(uint2*)h;
    *(uint2*)(lo + i4 * 4) = *(uint2*)l;
}

// ---------------- transpose + round to single fp16 --------------------------
__global__ __launch_bounds__(256) void transpose_f16(const float* __restrict__ in,
                                                     f16* __restrict__ out,
                                                     int R, int Cc)
{
    __shared__ float t[32][33];
    const int c = blockIdx.x * 32 + threadIdx.x;
    const int r0 = blockIdx.y * 32 + threadIdx.y;
#pragma unroll
    for (int i = 0; i < 4; ++i)
        t[threadIdx.y + i * 8][threadIdx.x] = in[(size_t)(r0 + i * 8) * Cc + c];
    __syncthreads();
    const int rc = blockIdx.y * 32 + threadIdx.x;
    const int c0 = blockIdx.x * 32 + threadIdx.y;
#pragma unroll
    for (int i = 0; i < 4; ++i)
        out[(size_t)(c0 + i * 8) * R + rc] = __float2half_rn(t[threadIdx.x][threadIdx.y + i * 8]);
}

// ---------------- tensor-core flash attention (causal, bf16x3) --------------
#define QSTR 136
#define VSTR 72
#define oQH 0
#define oQL (oQH + 128 * QSTR * 2)
#define oKH (oQL + 128 * QSTR * 2)
#define oKL (oKH + 2 * 64 * QSTR * 2)
#define oVH (oKL + 2 * 64 * QSTR * 2)
#define oVL (oVH + 2 * 128 * VSTR * 2)
#define ATT_SMEM (oVL + 2 * 128 * VSTR * 2)

__global__ __launch_bounds__(256, 1) void flash_mma(const bf16* __restrict__ QHg,
                                                    const bf16* __restrict__ QLg,
                                                    const bf16* __restrict__ KHg,
                                                    const bf16* __restrict__ KLg,
                                                    const bf16* __restrict__ VtHg,
                                                    const bf16* __restrict__ VtLg,
                                                    f16* __restrict__ attnH,
                                                    f16* __restrict__ attnL)
{
    extern __shared__ char asm_buf[];
    const uint32_t sb = smem_u32_of(asm_buf);

    const int tid = threadIdx.x;
    const int warp = tid >> 5, lane = tid & 31;
    const int g = lane >> 2;
    const int lam = lane & 3;
    const int lrow = lane & 15;
    const int lkh = (lane >> 4) << 3;

    const int qt = (int)(gridDim.x - 1 - blockIdx.x);
    const int h = blockIdx.y;
    const int b = blockIdx.z;
    const int qb = qt * 128;
    const size_t hoff = (size_t)(b * NHEAD + h) * SEQ * HDIM;
    const size_t voff = (size_t)(b * NHEAD + h) * HDIM * SEQ;

#pragma unroll
    for (int j = 0; j < 8; ++j) {
        const int i = tid + j * 256;
        const int row = i >> 4;
        const int seg = (i & 15) << 3;
        const uint32_t doff = (uint32_t)(row * QSTR + seg) * 2;
        const size_t soff = hoff + (size_t)(qb + row) * HDIM + seg;
        cp16(sb + oQH + doff, QHg + soff);
        cp16(sb + oQL + doff, QLg + soff);
    }
    cp_commit();

    const int ktmax = 2 * qt + 1;

    auto issueKV = [&](int kt, int buf) {
        const int kb = kt * 64;
#pragma unroll
        for (int j = 0; j < 4; ++j) {
            const int i = tid + j * 256;
            const int krow = i >> 4;
            const int kseg = (i & 15) << 3;
            const uint32_t kdoff = (uint32_t)(krow * QSTR + kseg) * 2;
            const size_t ksoff = hoff + (size_t)(kb + krow) * HDIM + kseg;
            cp16(sb + oKH + buf * (64 * QSTR * 2) + kdoff, KHg + ksoff);
            cp16(sb + oKL + buf * (64 * QSTR * 2) + kdoff, KLg + ksoff);
            const int vrow = i >> 3;
            const int vseg = (i & 7) << 3;
            const uint32_t vdoff = (uint32_t)(vrow * VSTR + vseg) * 2;
            const size_t vsoff = voff + (size_t)vrow * SEQ + kb + vseg;
            cp16(sb + oVH + buf * (128 * VSTR * 2) + vdoff, VtHg + vsoff);
            cp16(sb + oVL + buf * (128 * VSTR * 2) + vdoff, VtLg + vsoff);
        }
    };

    issueKV(0, 0);
    cp_commit();

    float oacc[16][4];
#pragma unroll
    for (int n = 0; n < 16; ++n)
#pragma unroll
        for (int i = 0; i < 4; ++i) oacc[n][i] = 0.f;
    float m0 = -1e30f, m1 = -1e30f, l0 = 0.f, l1 = 0.f;
    const float scale2 = 0.1275174324f;   // (1/sqrt(128)) * log2(e)

    const int r0g = qb + warp * 16 + g;
    const int r1g = r0g + 8;

    for (int kt = 0; kt <= ktmax; ++kt) {
        const int kb = kt * 64;
        const int buf = kt & 1;

        cp_wait<0>();
        __syncthreads();
        if (kt < ktmax) { issueKV(kt + 1, buf ^ 1); cp_commit(); }

        const uint32_t uQH = sb + oQH, uQL = sb + oQL;
        const uint32_t uKH = sb + oKH + buf * (64 * QSTR * 2);
        const uint32_t uKL = sb + oKL + buf * (64 * QSTR * 2);
        const uint32_t uVH = sb + oVH + buf * (128 * VSTR * 2);
        const uint32_t uVL = sb + oVL + buf * (128 * VSTR * 2);

        float sacc[8][4];
#pragma unroll
        for (int n = 0; n < 8; ++n)
#pragma unroll
            for (int i = 0; i < 4; ++i) sacc[n][i] = 0.f;

#pragma unroll
        for (int ks = 0; ks < 8; ++ks) {
            uint32_t ah[4], al[4];
            const uint32_t aoff = (uint32_t)(((warp * 16 + lrow) * QSTR + ks * 16 + lkh) * 2);
            ldm_x4(ah, uQH + aoff);
            ldm_x4(al, uQL + aoff);
#pragma unroll
            for (int ntp = 0; ntp < 2; ++ntp) {
                const int nt0 = 2 * ntp, nt1 = 2 * ntp + 1;
                uint32_t bh0[4], bl0[4], bh1[4], bl1[4];
                const uint32_t b0off = (uint32_t)(((nt0 * 16 + lrow) * QSTR + ks * 16 + lkh) * 2);
                const uint32_t b1off = (uint32_t)(((nt1 * 16 + lrow) * QSTR + ks * 16 + lkh) * 2);
                ldm_x4(bh0, uKH + b0off);
                ldm_x4(bl0, uKL + b0off);
                ldm_x4(bh1, uKH + b1off);
                ldm_x4(bl1, uKL + b1off);
                mma_bf16(sacc[2 * nt0],     ah, bh0[0], bh0[2]);
                mma_bf16(sacc[2 * nt0 + 1], ah, bh0[1], bh0[3]);
                mma_bf16(sacc[2 * nt1],     ah, bh1[0], bh1[2]);
                mma_bf16(sacc[2 * nt1 + 1], ah, bh1[1], bh1[3]);
                mma_bf16(sacc[2 * nt0],     ah, bl0[0], bl0[2]);
                mma_bf16(sacc[2 * nt0 + 1], ah, bl0[1], bl0[3]);
                mma_bf16(sacc[2 * nt1],     ah, bl1[0], bl1[2]);
                mma_bf16(sacc[2 * nt1 + 1], ah, bl1[1], bl1[3]);
                mma_bf16(sacc[2 * nt0],     al, bh0[0], bh0[2]);
                mma_bf16(sacc[2 * nt0 + 1], al, bh0[1], bh0[3]);
                mma_bf16(sacc[2 * nt1],     al, bh1[0], bh1[2]);
                mma_bf16(sacc[2 * nt1 + 1], al, bh1[1], bh1[3]);
            }
        }

        const bool need_mask = (kt >= 2 * qt);
        float rm0 = -1e30f, rm1 = -1e30f;
#pragma unroll
        for (int j = 0; j < 8; ++j) {
            const int cg0 = kb + j * 8 + 2 * lam;
#pragma unroll
            for (int i = 0; i < 4; ++i) {
                float v = sacc[j][i] * scale2;
                if (need_mask) {
                    const int cg = cg0 + (i & 1);
                    const int rg = (i < 2) ? r0g : r1g;
                    if (cg > rg) v = -1e30f;
                }
                sacc[j][i] = v;
            }
            rm0 = fmaxf(rm0, fmaxf(sacc[j][0], sacc[j][1]));
            rm1 = fmaxf(rm1, fmaxf(sacc[j][2], sacc[j][3]));
        }
#pragma unroll
        for (int off = 1; off <= 2; off <<= 1) {
            rm0 = fmaxf(rm0, __shfl_xor_sync(0xffffffffu, rm0, off));
            rm1 = fmaxf(rm1, __shfl_xor_sync(0xffffffffu, rm1, off));
        }
        const float mn0 = fmaxf(m0, rm0);
        const float mn1 = fmaxf(m1, rm1);
        const float al0 = exp2f(m0 - mn0);
        const float al1 = exp2f(m1 - mn1);
        m0 = mn0; m1 = mn1;

        float rs0 = 0.f, rs1 = 0.f;
#pragma unroll
        for (int j = 0; j < 8; ++j) {
            sacc[j][0] = exp2f(sacc[j][0] - mn0);
            sacc[j][1] = exp2f(sacc[j][1] - mn0);
            sacc[j][2] = exp2f(sacc[j][2] - mn1);
            sacc[j][3] = exp2f(sacc[j][3] - mn1);
            rs0 += sacc[j][0] + sacc[j][1];
            rs1 += sacc[j][2] + sacc[j][3];
        }
#pragma unroll
        for (int off = 1; off <= 2; off <<= 1) {
            rs0 += __shfl_xor_sync(0xffffffffu, rs0, off);
            rs1 += __shfl_xor_sync(0xffffffffu, rs1, off);
        }
        l0 = l0 * al0 + rs0;
        l1 = l1 * al1 + rs1;

#pragma unroll
        for (int n = 0; n < 16; ++n) {
            oacc[n][0] *= al0; oacc[n][1] *= al0;
            oacc[n][2] *= al1; oacc[n][3] *= al1;
        }

        uint32_t pah[4][4], pal[4][4];
#pragma unroll
        for (int j2 = 0; j2 < 4; ++j2) {
            float p00 = sacc[2 * j2][0],     p01 = sacc[2 * j2][1];
            float p02 = sacc[2 * j2][2],     p03 = sacc[2 * j2][3];
            float p10 = sacc[2 * j2 + 1][0], p11 = sacc[2 * j2 + 1][1];
            float p12 = sacc[2 * j2 + 1][2], p13 = sacc[2 * j2 + 1][3];
            pah[j2][0] = pk2(p00, p01);
            pah[j2][1] = pk2(p02, p03);
            pah[j2][2] = pk2(p10, p11);
            pah[j2][3] = pk2(p12, p13);
            bf16 hh;
            hh = __float2bfloat16_rn(p00); p00 -= __bfloat162float(hh);
            hh = __float2bfloat16_rn(p01); p01 -= __bfloat162float(hh);
            hh = __float2bfloat16_rn(p02); p02 -= __bfloat162float(hh);
            hh = __float2bfloat16_rn(p03); p03 -= __bfloat162float(hh);
            hh = __float2bfloat16_rn(p10); p10 -= __bfloat162float(hh);
            hh = __float2bfloat16_rn(p11); p11 -= __bfloat162float(hh);
            hh = __float2bfloat16_rn(p12); p12 -= __bfloat162float(hh);
            hh = __float2bfloat16_rn(p13); p13 -= __bfloat162float(hh);
            pal[j2][0] = pk2(p00, p01);
            pal[j2][1] = pk2(p02, p03);
            pal[j2][2] = pk2(p10, p11);
            pal[j2][3] = pk2(p12, p13);
        }

#pragma unroll
        for (int ntp = 0; ntp < 4; ++ntp) {
            const int nt0 = 2 * ntp, nt1 = 2 * ntp + 1;
#pragma unroll
            for (int j2 = 0; j2 < 4; ++j2) {
                uint32_t vh0[4], vl0[4], vh1[4], vl1[4];
                const uint32_t v0off = (uint32_t)(((nt0 * 16 + lrow) * VSTR + j2 * 16 + lkh) * 2);
                const uint32_t v1off = (uint32_t)(((nt1 * 16 + lrow) * VSTR + j2 * 16 + lkh) * 2);
                ldm_x4(vh0, uVH + v0off);
                ldm_x4(vl0, uVL + v0off);
                ldm_x4(vh1, uVH + v1off);
                ldm_x4(vl1, uVL + v1off);
                mma_bf16(oacc[2 * nt0],     pah[j2], vh0[0], vh0[2]);
                mma_bf16(oacc[2 * nt0 + 1], pah[j2], vh0[1], vh0[3]);
                mma_bf16(oacc[2 * nt1],     pah[j2], vh1[0], vh1[2]);
                mma_bf16(oacc[2 * nt1 + 1], pah[j2], vh1[1], vh1[3]);
                mma_bf16(oacc[2 * nt0],     pah[j2], vl0[0], vl0[2]);
                mma_bf16(oacc[2 * nt0 + 1], pah[j2], vl0[1], vl0[3]);
                mma_bf16(oacc[2 * nt1],     pah[j2], vl1[0], vl1[2]);
                mma_bf16(oacc[2 * nt1 + 1], pah[j2], vl1[1], vl1[3]);
                mma_bf16(oacc[2 * nt0],     pal[j2], vh0[0], vh0[2]);
                mma_bf16(oacc[2 * nt0 + 1], pal[j2], vh0[1], vh0[3]);
                mma_bf16(oacc[2 * nt1],     pal[j2], vh1[0], vh1[2]);
                mma_bf16(oacc[2 * nt1 + 1], pal[j2], vh1[1], vh1[3]);
            }
        }
    }

    // epilogue: normalize, split to fp16 hi/lo for the O-proj
    const float i0 = 1.0f / l0;
    const float i1 = 1.0f / l1;
    const size_t row0 = ((size_t)b * SEQ + r0g) * HID + h * HDIM;
    const size_t row1 = ((size_t)b * SEQ + r1g) * HID + h * HDIM;
#pragma unroll
    for (int n = 0; n < 16; ++n) {
        const int col = n * 8 + 2 * lam;
        float x0 = oacc[n][0] * i0, x1 = oacc[n][1] * i0;
        float y0 = oacc[n][2] * i1, y1 = oacc[n][3] * i1;
        *(uint32_t*)(attnH + row0 + col) = pk2h(x0, x1);
        *(uint32_t*)(attnH + row1 + col) = pk2h(y0, y1);
        f16 hb;
        hb = __float2half_rn(x0); x0 -= __half2float(hb);
        hb = __float2half_rn(x1); x1 -= __half2float(hb);
        hb = __float2half_rn(y0); y0 -= __half2float(hb);
        hb = __float2half_rn(y1); y1 -= __half2float(hb);
        *(uint32_t*)(attnL + row0 + col) = pk2h(x0, x1);
        *(uint32_t*)(attnL + row1 + col) = pk2h(y0, y1);
    }
}

// ---------------------------------------------------------------------------
extern "C" void kernel_launch(void* const* d_in, const int* in_sizes, int n_in,
                              void* d_out, int out_size)
{
    (void)in_sizes; (void)n_in; (void)out_size;
    const float* hidden = (const float*)d_in[0];
    const float* w_qkv  = (const float*)d_in[1];
    const float* w_o    = (const float*)d_in[2];
    const int*   pos    = (const int*)d_in[3];
    float* out = (float*)d_out;

    f16 *hidH, *hidL, *wqkvt, *wot, *attnH, *attnL;
    bf16 *QH, *QL, *KH, *KL, *VtH, *VtL;
    float *ctab, *stab;
    cudaGetSymbolAddress((void**)&hidH,  g_hidH);
    cudaGetSymbolAddress((void**)&hidL,  g_hidL);
    cudaGetSymbolAddress((void**)&wqkvt, g_wqkvt);
    cudaGetSymbolAddress((void**)&wot,   g_wot);
    cudaGetSymbolAddress((void**)&ctab,  g_ctab);
    cudaGetSymbolAddress((void**)&stab,  g_stab);
    cudaGetSymbolAddress((void**)&QH,    g_QH);
    cudaGetSymbolAddress((void**)&QL,    g_QL);
    cudaGetSymbolAddress((void**)&KH,    g_KH);
    cudaGetSymbolAddress((void**)&KL,    g_KL);
    cudaGetSymbolAddress((void**)&VtH,   g_VtH);
    cudaGetSymbolAddress((void**)&VtL,   g_VtL);
    cudaGetSymbolAddress((void**)&attnH, g_attnH);
    cudaGetSymbolAddress((void**)&attnL, g_attnL);

    // 0) preprocessing
    split_f32h<<<(TOKENS * HID) / 1024, 256>>>(hidden, hidH, hidL);
    transpose_f16<<<dim3(QKVN / 32, HID / 32), dim3(32, 8)>>>(w_qkv, wqkvt, HID, QKVN);
    transpose_f16<<<dim3(HID / 32, HID / 32), dim3(32, 8)>>>(w_o, wot, HID, HID);
    rope_tab<<<TOKENS, 64>>>(pos, ctab, stab);

    const int gsmem = NSTG * STG_BYTES;   // 98304 -> 2 CTAs/SM
    cudaFuncSetAttribute(gemm_f16x2, cudaFuncAttributeMaxDynamicSharedMemorySize, gsmem);

    // 1) QKV projection fused with RoPE + head-split + V-transpose (mode 1)
    gemm_f16x2<<<(TOKENS / 128) * (QKVN / 128), 256, gsmem>>>(
        hidH, hidL, wqkvt, nullptr, ctab, stab,
        QH, QL, KH, KL, VtH, VtL,
        TOKENS, QKVN, HID, TOKENS / 128, 1);

    // 2) tensor-core causal flash attention -> fp16-split attn
    cudaFuncSetAttribute(flash_mma, cudaFuncAttributeMaxDynamicSharedMemorySize, ATT_SMEM);
    flash_mma<<<dim3(SEQ / 128, NHEAD, BATCH), 256, ATT_SMEM>>>(
        QH, QL, KH, KL, VtH, VtL, attnH, attnL);

    // 3) output projection (mode 0)
    gemm_f16x2<<<(TOKENS / 128) * (HID / 128), 256, gsmem>>>(
        attnH, attnL, wot, out, nullptr, nullptr,
        nullptr, nullptr, nullptr, nullptr, nullptr, nullptr,
        TOKENS, HID, HID, TOKENS / 128, 0);
}

// round 12
// speedup vs baseline: 1.1212x; 1.0180x over previous
#include <cuda_runtime.h>
#include <cuda_bf16.h>
#include <cuda_fp16.h>
#include <math.h>
#include <stdint.h>

#define BATCH 2
#define SEQ   2048
#define HID   4096
#define NHEAD 32
#define HDIM  128
#define TOKENS (BATCH * SEQ)     // 4096
#define QKVN  (3 * HID)          // 12288
#define HEADS (BATCH * NHEAD)    // 64

typedef __nv_bfloat16 bf16;
typedef __half f16;

// ---------------- scratch (device globals; no allocation allowed) ----------
__device__ f16   g_hidH[(size_t)TOKENS * HID];
__device__ f16   g_hidL[(size_t)TOKENS * HID];
__device__ f16   g_wqkvt[(size_t)QKVN * HID];
__device__ f16   g_wot[(size_t)HID * HID];
__device__ float g_ctab[(size_t)TOKENS * 64];
__device__ float g_stab[(size_t)TOKENS * 64];
__device__ bf16  g_QH[(size_t)HEADS * SEQ * HDIM];
__device__ bf16  g_QL[(size_t)HEADS * SEQ * HDIM];
__device__ bf16  g_KH[(size_t)HEADS * SEQ * HDIM];
__device__ bf16  g_KL[(size_t)HEADS * SEQ * HDIM];
__device__ bf16  g_VtH[(size_t)HEADS * HDIM * SEQ];
__device__ bf16  g_VtL[(size_t)HEADS * HDIM * SEQ];
__device__ f16   g_attnH[(size_t)TOKENS * HID];
__device__ f16   g_attnL[(size_t)TOKENS * HID];

// ======================= helpers ==================================
__device__ __forceinline__ uint32_t smem_u32_of(const void* p) {
    uint32_t a;
    asm("{ .reg .u64 t; cvta.to.shared.u64 t, %1; cvt.u32.u64 %0, t; }" : "=r"(a) : "l"(p));
    return a;
}
__device__ __forceinline__ void ldm_x4(uint32_t* r, uint32_t addr) {
    asm volatile("ldmatrix.sync.aligned.m8n8.x4.shared.b16 {%0,%1,%2,%3}, [%4];"
                 : "=r"(r[0]), "=r"(r[1]), "=r"(r[2]), "=r"(r[3]) : "r"(addr));
}
__device__ __forceinline__ void mma_bf16(float* d, const uint32_t* a, uint32_t b0, uint32_t b1) {
    asm volatile(
        "mma.sync.aligned.m16n8k16.row.col.f32.bf16.bf16.f32 "
        "{%0,%1,%2,%3},{%4,%5,%6,%7},{%8,%9},{%0,%1,%2,%3};"
        : "+f"(d[0]), "+f"(d[1]), "+f"(d[2]), "+f"(d[3])
        : "r"(a[0]), "r"(a[1]), "r"(a[2]), "r"(a[3]), "r"(b0), "r"(b1));
}
__device__ __forceinline__ void mma_f16(float* d, const uint32_t* a, uint32_t b0, uint32_t b1) {
    asm volatile(
        "mma.sync.aligned.m16n8k16.row.col.f32.f16.f16.f32 "
        "{%0,%1,%2,%3},{%4,%5,%6,%7},{%8,%9},{%0,%1,%2,%3};"
        : "+f"(d[0]), "+f"(d[1]), "+f"(d[2]), "+f"(d[3])
        : "r"(a[0]), "r"(a[1]), "r"(a[2]), "r"(a[3]), "r"(b0), "r"(b1));
}
__device__ __forceinline__ void bfsplit(float x, bf16& hi, bf16& lo) {
    hi = __float2bfloat16_rn(x);
    lo = __float2bfloat16_rn(x - __bfloat162float(hi));
}
__device__ __forceinline__ void hsplit(float x, f16& hi, f16& lo) {
    hi = __float2half_rn(x);
    lo = __float2half_rn(x - __half2float(hi));
}
__device__ __forceinline__ uint32_t pk2(float a, float b) {
    __nv_bfloat162 t = __floats2bfloat162_rn(a, b);
    return *(uint32_t*)&t;
}
__device__ __forceinline__ uint32_t pk2h(float a, float b) {
    __half2 t = __floats2half2_rn(a, b);
    return *(uint32_t*)&t;
}
__device__ __forceinline__ void cp16(uint32_t smem, const void* g) {
    asm volatile("cp.async.cg.shared.global [%0], [%1], 16;" :: "r"(smem), "l"(g) : "memory");
}
__device__ __forceinline__ void cp_commit() {
    asm volatile("cp.async.commit_group;" ::: "memory");
}
template <int N> __device__ __forceinline__ void cp_wait() {
    asm volatile("cp.async.wait_group %0;" :: "n"(N) : "memory");
}

// ============ fp16 2-term compensated tensor-core GEMM ======================
// tile 128x128, KC=64, 256 threads, NSTG=2, 2 CTAs/SM, per-CTA K-phase rotation.
#define KC  64
#define STG_ARR (128 * KC * 2)       // 16384 B
#define STG_BYTES (3 * STG_ARR)      // 49152 B (Ah, Al, Bh)
#define NSTG 2
#define EPAD 129

__global__ __launch_bounds__(256, 2) void gemm_f16x2(const f16* __restrict__ Ah,
                                                     const f16* __restrict__ Al,
                                                     const f16* __restrict__ Bh,
                                                     float* __restrict__ C,
                                                     const float* __restrict__ ctab,
                                                     const float* __restrict__ stab,
                                                     bf16* __restrict__ QH, bf16* __restrict__ QL,
                                                     bf16* __restrict__ KH, bf16* __restrict__ KL,
                                                     bf16* __restrict__ VtH, bf16* __restrict__ VtL,
                                                     int M, int N, int K, int Mtiles, int mode)
{
    extern __shared__ char gsm[];
    const uint32_t sbase = smem_u32_of(gsm);

    const int tid = threadIdx.x;
    const int warp = tid >> 5, lane = tid & 31;
    const int wm = warp & 3;
    const int wn = warp >> 2;

    const int bx = blockIdx.x;
    const int group = bx / (Mtiles * 8);
    const int rr = bx % (Mtiles * 8);
    const int bm = rr % Mtiles;
    const int bn = group * 8 + rr / Mtiles;

    const f16* Aph = Ah + (size_t)bm * 128 * K;
    const f16* Apl = Al + (size_t)bm * 128 * K;
    const f16* Bph = Bh + (size_t)bn * 128 * K;

    const int lrow = lane & 15;
    const int lc_half = lane >> 4;

    float acc[2][8][4];
#pragma unroll
    for (int t = 0; t < 2; ++t)
#pragma unroll
        for (int n = 0; n < 8; ++n)
#pragma unroll
            for (int i = 0; i < 4; ++i) acc[t][n][i] = 0.f;

    const int nc = K / KC;   // 64
    // per-CTA K-phase: de-correlates co-resident CTAs' barrier arrivals
    const int phase = (bx & 3) * (nc >> 2);

    auto issue = [&](int c, int st) {
        const int kc = c * KC;
        const uint32_t sb = sbase + st * STG_BYTES;
#pragma unroll
        for (int q = 0; q < 4; ++q) {
            const int i = tid + q * 256;
            const int row = i >> 3;
            const int chunk = i & 7;
            const int pchunk = chunk ^ (row & 7);
            const uint32_t doff = (uint32_t)(row * 128 + pchunk * 16);
            const size_t soff = (size_t)row * K + kc + chunk * 8;
            cp16(sb + 0 * STG_ARR + doff, Aph + soff);
            cp16(sb + 1 * STG_ARR + doff, Apl + soff);
            cp16(sb + 2 * STG_ARR + doff, Bph + soff);
        }
    };

    issue(phase, 0); cp_commit();

    for (int cc = 0; cc < nc; ++cc) {
        cp_wait<0>();
        __syncthreads();
        if (cc + 1 < nc) {
            int cn = cc + 1 + phase;
            if (cn >= nc) cn -= nc;
            issue(cn, (cc + 1) & 1);
            cp_commit();
        }

        const int st = cc & 1;
        const uint32_t uAh = sbase + st * STG_BYTES;
        const uint32_t uAl = uAh + STG_ARR;
        const uint32_t uBh = uAh + 2 * STG_ARR;

#pragma unroll
        for (int ks = 0; ks < 4; ++ks) {
            const int lc = ks * 2 + lc_half;
            uint32_t ah[2][4], al[2][4];
#pragma unroll
            for (int t = 0; t < 2; ++t) {
                const int ar = wm * 32 + t * 16 + lrow;
                const uint32_t aoff = (uint32_t)(ar * 128 + (lc ^ (ar & 7)) * 16);
                ldm_x4(ah[t], uAh + aoff);
                ldm_x4(al[t], uAl + aoff);
            }
#pragma unroll
            for (int nt = 0; nt < 4; ++nt) {
                const int br = wn * 64 + nt * 16 + lrow;
                const uint32_t boff = (uint32_t)(br * 128 + (lc ^ (br & 7)) * 16);
                uint32_t bh[4];
                ldm_x4(bh, uBh + boff);
                mma_f16(acc[0][2 * nt],     ah[0], bh[0], bh[2]);
                mma_f16(acc[1][2 * nt],     ah[1], bh[0], bh[2]);
                mma_f16(acc[0][2 * nt + 1], ah[0], bh[1], bh[3]);
                mma_f16(acc[1][2 * nt + 1], ah[1], bh[1], bh[3]);
                mma_f16(acc[0][2 * nt],     al[0], bh[0], bh[2]);
                mma_f16(acc[1][2 * nt],     al[1], bh[0], bh[2]);
                mma_f16(acc[0][2 * nt + 1], al[0], bh[1], bh[3]);
                mma_f16(acc[1][2 * nt + 1], al[1], bh[1], bh[3]);
            }
        }
    }

    const int g = lane >> 2;
    const int tc2 = (lane & 3) << 1;

    if (mode == 0) {
#pragma unroll
        for (int t = 0; t < 2; ++t) {
            const int row0 = bm * 128 + wm * 32 + t * 16 + g;
#pragma unroll
            for (int n = 0; n < 8; ++n) {
                const int col = bn * 128 + wn * 64 + n * 8 + tc2;
                *(float2*)(C + (size_t)row0 * N + col) = make_float2(acc[t][n][0], acc[t][n][1]);
                *(float2*)(C + (size_t)(row0 + 8) * N + col) = make_float2(acc[t][n][2], acc[t][n][3]);
            }
        }
        return;
    }

    // -------- fused QKV epilogue ---------------------------------------------
    float* spad = (float*)gsm;
    __syncthreads();
#pragma unroll
    for (int t = 0; t < 2; ++t) {
        const int r0 = wm * 32 + t * 16 + g;
#pragma unroll
        for (int n = 0; n < 8; ++n) {
            const int col = wn * 64 + n * 8 + tc2;
            spad[r0 * EPAD + col]           = acc[t][n][0];
            spad[r0 * EPAD + col + 1]       = acc[t][n][1];
            spad[(r0 + 8) * EPAD + col]     = acc[t][n][2];
            spad[(r0 + 8) * EPAD + col + 1] = acc[t][n][3];
        }
    }
    __syncthreads();

    const int region = bn >> 5;      // 0:Q 1:K 2:V
    const int head = bn & 31;

    if (region < 2) {
        bf16* OH = region ? KH : QH;
        bf16* OL = region ? KL : QL;
#pragma unroll
        for (int q = 0; q < 32; ++q) {
            const int p = tid + q * 256;
            const int tok = p >> 6;
            const int i = p & 63;
            const int gtok = bm * 128 + tok;
            const float x1 = spad[tok * EPAD + i];
            const float x2 = spad[tok * EPAD + 64 + i];
            const float cv = ctab[(size_t)gtok * 64 + i];
            const float sv = stab[(size_t)gtok * 64 + i];
            const float r1 = x1 * cv - x2 * sv;
            const float r2 = x2 * cv + x1 * sv;
            const int bb = gtok >> 11;
            const int ss = gtok & 2047;
            const size_t ob = ((size_t)(bb * NHEAD + head) * SEQ + ss) * HDIM;
            bf16 hh, ll;
            bfsplit(r1, hh, ll); OH[ob + i] = hh;      OL[ob + i] = ll;
            bfsplit(r2, hh, ll); OH[ob + 64 + i] = hh; OL[ob + 64 + i] = ll;
        }
    } else {
#pragma unroll
        for (int q = 0; q < 64; ++q) {
            const int p = tid + q * 256;
            const int tok = p & 127;
            const int d = p >> 7;
            const int gtok = bm * 128 + tok;
            const float v = spad[tok * EPAD + d];
            const int bb = gtok >> 11;
            const int ss = gtok & 2047;
            const size_t od = ((size_t)(bb * NHEAD + head) * HDIM + d) * SEQ + ss;
            bf16 hh, ll;
            bfsplit(v, hh, ll);
            VtH[od] = hh;
            VtL[od] = ll;
        }
    }
}

// ---------------- RoPE cos/sin table (fp64 reduce + fp32 trig) --------------
__global__ __launch_bounds__(256) void rope_tab(const int* __restrict__ pos,
                                                float* __restrict__ ct,
                                                float* __restrict__ st)
{
    const int idx = blockIdx.x * 256 + threadIdx.x;   // over TOKENS*64
    const int tok = idx >> 6;
    const int i = idx & 63;
    double inv = exp(-9.210340371976184 * ((double)(2 * i) / 128.0));
    double ang = (double)pos[tok] * inv;
    double r = remainder(ang, 6.283185307179586476925286766559);
    float rf = (float)r;
    ct[idx] = cosf(rf);
    st[idx] = sinf(rf);
}

// ---------------- elementwise split fp32 -> fp16 hi/lo ----------------------
__global__ __launch_bounds__(256) void split_f32h(const float* __restrict__ in,
                                                  f16* __restrict__ hi,
                                                  f16* __restrict__ lo)
{
    const size_t i4 = (size_t)blockIdx.x * 256 + threadIdx.x;
    float4 v = *(const float4*)(in + i4 * 4);
    f16 h[4], l[4];
    hsplit(v.x, h[0], l[0]); hsplit(v.y, h[1], l[1]);
    hsplit(v.z, h[2], l[2]); hsplit(v.w, h[3], l[3]);
    *(uint2*)(hi + i4 * 4) = *(uint2*)h;
    *(uint2*)(lo + i4 * 4) = *(uint2*)l;
}

// ---------------- transpose + round to single fp16 --------------------------
__global__ __launch_bounds__(256) void transpose_f16(const float* __restrict__ in,
                                                     f16* __restrict__ out,
                                                     int R, int Cc)
{
    __shared__ float t[32][33];
    const int c = blockIdx.x * 32 + threadIdx.x;
    const int r0 = blockIdx.y * 32 + threadIdx.y;
#pragma unroll
    for (int i = 0; i < 4; ++i)
        t[threadIdx.y + i * 8][threadIdx.x] = in[(size_t)(r0 + i * 8) * Cc + c];
    __syncthreads();
    const int rc = blockIdx.y * 32 + threadIdx.x;
    const int c0 = blockIdx.x * 32 + threadIdx.y;
#pragma unroll
    for (int i = 0; i < 4; ++i)
        out[(size_t)(c0 + i * 8) * R + rc] = __float2half_rn(t[threadIdx.x][threadIdx.y + i * 8]);
}

// ---------------- tensor-core flash attention (causal, bf16x3) --------------
#define QSTR 136
#define VSTR 72
#define oQH 0
#define oQL (oQH + 128 * QSTR * 2)
#define oKH (oQL + 128 * QSTR * 2)
#define oKL (oKH + 2 * 64 * QSTR * 2)
#define oVH (oKL + 2 * 64 * QSTR * 2)
#define oVL (oVH + 2 * 128 * VSTR * 2)
#define ATT_SMEM (oVL + 2 * 128 * VSTR * 2)

__global__ __launch_bounds__(256, 1) void flash_mma(const bf16* __restrict__ QHg,
                                                    const bf16* __restrict__ QLg,
                                                    const bf16* __restrict__ KHg,
                                                    const bf16* __restrict__ KLg,
                                                    const bf16* __restrict__ VtHg,
                                                    const bf16* __restrict__ VtLg,
                                                    f16* __restrict__ attnH,
                                                    f16* __restrict__ attnL)
{
    extern __shared__ char asm_buf[];
    const uint32_t sb = smem_u32_of(asm_buf);

    const int tid = threadIdx.x;
    const int warp = tid >> 5, lane = tid & 31;
    const int g = lane >> 2;
    const int lam = lane & 3;
    const int lrow = lane & 15;
    const int lkh = (lane >> 4) << 3;

    const int qt = (int)(gridDim.x - 1 - blockIdx.x);
    const int h = blockIdx.y;
    const int b = blockIdx.z;
    const int qb = qt * 128;
    const size_t hoff = (size_t)(b * NHEAD + h) * SEQ * HDIM;
    const size_t voff = (size_t)(b * NHEAD + h) * HDIM * SEQ;

#pragma unroll
    for (int j = 0; j < 8; ++j) {
        const int i = tid + j * 256;
        const int row = i >> 4;
        const int seg = (i & 15) << 3;
        const uint32_t doff = (uint32_t)(row * QSTR + seg) * 2;
        const size_t soff = hoff + (size_t)(qb + row) * HDIM + seg;
        cp16(sb + oQH + doff, QHg + soff);
        cp16(sb + oQL + doff, QLg + soff);
    }
    cp_commit();

    const int ktmax = 2 * qt + 1;

    auto issueKV = [&](int kt, int buf) {
        const int kb = kt * 64;
#pragma unroll
        for (int j = 0; j < 4; ++j) {
            const int i = tid + j * 256;
            const int krow = i >> 4;
            const int kseg = (i & 15) << 3;
            const uint32_t kdoff = (uint32_t)(krow * QSTR + kseg) * 2;
            const size_t ksoff = hoff + (size_t)(kb + krow) * HDIM + kseg;
            cp16(sb + oKH + buf * (64 * QSTR * 2) + kdoff, KHg + ksoff);
            cp16(sb + oKL + buf * (64 * QSTR * 2) + kdoff, KLg + ksoff);
            const int vrow = i >> 3;
            const int vseg = (i & 7) << 3;
            const uint32_t vdoff = (uint32_t)(vrow * VSTR + vseg) * 2;
            const size_t vsoff = voff + (size_t)vrow * SEQ + kb + vseg;
            cp16(sb + oVH + buf * (128 * VSTR * 2) + vdoff, VtHg + vsoff);
            cp16(sb + oVL + buf * (128 * VSTR * 2) + vdoff, VtLg + vsoff);
        }
    };

    issueKV(0, 0);
    cp_commit();

    float oacc[16][4];
#pragma unroll
    for (int n = 0; n < 16; ++n)
#pragma unroll
        for (int i = 0; i < 4; ++i) oacc[n][i] = 0.f;
    float m0 = -1e30f, m1 = -1e30f, l0 = 0.f, l1 = 0.f;
    const float scale2 = 0.1275174324f;

    const int r0g = qb + warp * 16 + g;
    const int r1g = r0g + 8;

    for (int kt = 0; kt <= ktmax; ++kt) {
        const int kb = kt * 64;
        const int buf = kt & 1;

        cp_wait<0>();
        __syncthreads();
        if (kt < ktmax) { issueKV(kt + 1, buf ^ 1); cp_commit(); }

        const uint32_t uQH = sb + oQH, uQL = sb + oQL;
        const uint32_t uKH = sb + oKH + buf * (64 * QSTR * 2);
        const uint32_t uKL = sb + oKL + buf * (64 * QSTR * 2);
        const uint32_t uVH = sb + oVH + buf * (128 * VSTR * 2);
        const uint32_t uVL = sb + oVL + buf * (128 * VSTR * 2);

        float sacc[8][4];
#pragma unroll
        for (int n = 0; n < 8; ++n)
#pragma unroll
            for (int i = 0; i < 4; ++i) sacc[n][i] = 0.f;

#pragma unroll
        for (int ks = 0; ks < 8; ++ks) {
            uint32_t ah[4], al[4];
            const uint32_t aoff = (uint32_t)(((warp * 16 + lrow) * QSTR + ks * 16 + lkh) * 2);
            ldm_x4(ah, uQH + aoff);
            ldm_x4(al, uQL + aoff);
#pragma unroll
            for (int ntp = 0; ntp < 2; ++ntp) {
                const int nt0 = 2 * ntp, nt1 = 2 * ntp + 1;
                uint32_t bh0[4], bl0[4], bh1[4], bl1[4];
                const uint32_t b0off = (uint32_t)(((nt0 * 16 + lrow) * QSTR + ks * 16 + lkh) * 2);
                const uint32_t b1off = (uint32_t)(((nt1 * 16 + lrow) * QSTR + ks * 16 + lkh) * 2);
                ldm_x4(bh0, uKH + b0off);
                ldm_x4(bl0, uKL + b0off);
                ldm_x4(bh1, uKH + b1off);
                ldm_x4(bl1, uKL + b1off);
                mma_bf16(sacc[2 * nt0],     ah, bh0[0], bh0[2]);
                mma_bf16(sacc[2 * nt0 + 1], ah, bh0[1], bh0[3]);
                mma_bf16(sacc[2 * nt1],     ah, bh1[0], bh1[2]);
                mma_bf16(sacc[2 * nt1 + 1], ah, bh1[1], bh1[3]);
                mma_bf16(sacc[2 * nt0],     ah, bl0[0], bl0[2]);
                mma_bf16(sacc[2 * nt0 + 1], ah, bl0[1], bl0[3]);
                mma_bf16(sacc[2 * nt1],     ah, bl1[0], bl1[2]);
                mma_bf16(sacc[2 * nt1 + 1], ah, bl1[1], bl1[3]);
                mma_bf16(sacc[2 * nt0],     al, bh0[0], bh0[2]);
                mma_bf16(sacc[2 * nt0 + 1], al, bh0[1], bh0[3]);
                mma_bf16(sacc[2 * nt1],     al, bh1[0], bh1[2]);
                mma_bf16(sacc[2 * nt1 + 1], al, bh1[1], bh1[3]);
            }
        }

        const bool need_mask = (kt >= 2 * qt);
        float rm0 = -1e30f, rm1 = -1e30f;
#pragma unroll
        for (int j = 0; j < 8; ++j) {
            const int cg0 = kb + j * 8 + 2 * lam;
#pragma unroll
            for (int i = 0; i < 4; ++i) {
                float v = sacc[j][i] * scale2;
                if (need_mask) {
                    const int cg = cg0 + (i & 1);
                    const int rg = (i < 2) ? r0g : r1g;
                    if (cg > rg) v = -1e30f;
                }
                sacc[j][i] = v;
            }
            rm0 = fmaxf(rm0, fmaxf(sacc[j][0], sacc[j][1]));
            rm1 = fmaxf(rm1, fmaxf(sacc[j][2], sacc[j][3]));
        }
#pragma unroll
        for (int off = 1; off <= 2; off <<= 1) {
            rm0 = fmaxf(rm0, __shfl_xor_sync(0xffffffffu, rm0, off));
            rm1 = fmaxf(rm1, __shfl_xor_sync(0xffffffffu, rm1, off));
        }
        const float mn0 = fmaxf(m0, rm0);
        const float mn1 = fmaxf(m1, rm1);
        const float al0 = exp2f(m0 - mn0);
        const float al1 = exp2f(m1 - mn1);
        m0 = mn0; m1 = mn1;

        float rs0 = 0.f, rs1 = 0.f;
#pragma unroll
        for (int j = 0; j < 8; ++j) {
            sacc[j][0] = exp2f(sacc[j][0] - mn0);
            sacc[j][1] = exp2f(sacc[j][1] - mn0);
            sacc[j][2] = exp2f(sacc[j][2] - mn1);
            sacc[j][3] = exp2f(sacc[j][3] - mn1);
            rs0 += sacc[j][0] + sacc[j][1];
            rs1 += sacc[j][2] + sacc[j][3];
        }
#pragma unroll
        for (int off = 1; off <= 2; off <<= 1) {
            rs0 += __shfl_xor_sync(0xffffffffu, rs0, off);
            rs1 += __shfl_xor_sync(0xffffffffu, rs1, off);
        }
        l0 = l0 * al0 + rs0;
        l1 = l1 * al1 + rs1;

#pragma unroll
        for (int n = 0; n < 16; ++n) {
            oacc[n][0] *= al0; oacc[n][1] *= al0;
            oacc[n][2] *= al1; oacc[n][3] *= al1;
        }

        uint32_t pah[4][4], pal[4][4];
#pragma unroll
        for (int j2 = 0; j2 < 4; ++j2) {
            float p00 = sacc[2 * j2][0],     p01 = sacc[2 * j2][1];
            float p02 = sacc[2 * j2][2],     p03 = sacc[2 * j2][3];
            float p10 = sacc[2 * j2 + 1][0], p11 = sacc[2 * j2 + 1][1];
            float p12 = sacc[2 * j2 + 1][2], p13 = sacc[2 * j2 + 1][3];
            pah[j2][0] = pk2(p00, p01);
            pah[j2][1] = pk2(p02, p03);
            pah[j2][2] = pk2(p10, p11);
            pah[j2][3] = pk2(p12, p13);
            bf16 hh;
            hh = __float2bfloat16_rn(p00); p00 -= __bfloat162float(hh);
            hh = __float2bfloat16_rn(p01); p01 -= __bfloat162float(hh);
            hh = __float2bfloat16_rn(p02); p02 -= __bfloat162float(hh);
            hh = __float2bfloat16_rn(p03); p03 -= __bfloat162float(hh);
            hh = __float2bfloat16_rn(p10); p10 -= __bfloat162float(hh);
            hh = __float2bfloat16_rn(p11); p11 -= __bfloat162float(hh);
            hh = __float2bfloat16_rn(p12); p12 -= __bfloat162float(hh);
            hh = __float2bfloat16_rn(p13); p13 -= __bfloat162float(hh);
            pal[j2][0] = pk2(p00, p01);
            pal[j2][1] = pk2(p02, p03);
            pal[j2][2] = pk2(p10, p11);
            pal[j2][3] = pk2(p12, p13);
        }

#pragma unroll
        for (int ntp = 0; ntp < 4; ++ntp) {
            const int nt0 = 2 * ntp, nt1 = 2 * ntp + 1;
#pragma unroll
            for (int j2 = 0; j2 < 4; ++j2) {
                uint32_t vh0[4], vl0[4], vh1[4], vl1[4];
                const uint32_t v0off = (uint32_t)(((nt0 * 16 + lrow) * VSTR + j2 * 16 + lkh) * 2);
                const uint32_t v1off = (uint32_t)(((nt1 * 16 + lrow) * VSTR + j2 * 16 + lkh) * 2);
                ldm_x4(vh0, uVH + v0off);
                ldm_x4(vl0, uVL + v0off);
                ldm_x4(vh1, uVH + v1off);
                ldm_x4(vl1, uVL + v1off);
                mma_bf16(oacc[2 * nt0],     pah[j2], vh0[0], vh0[2]);
                mma_bf16(oacc[2 * nt0 + 1], pah[j2], vh0[1], vh0[3]);
                mma_bf16(oacc[2 * nt1],     pah[j2], vh1[0], vh1[2]);
                mma_bf16(oacc[2 * nt1 + 1], pah[j2], vh1[1], vh1[3]);
                mma_bf16(oacc[2 * nt0],     pah[j2], vl0[0], vl0[2]);
                mma_bf16(oacc[2 * nt0 + 1], pah[j2], vl0[1], vl0[3]);
                mma_bf16(oacc[2 * nt1],     pah[j2], vl1[0], vl1[2]);
                mma_bf16(oacc[2 * nt1 + 1], pah[j2], vl1[1], vl1[3]);
                mma_bf16(oacc[2 * nt0],     pal[j2], vh0[0], vh0[2]);
                mma_bf16(oacc[2 * nt0 + 1], pal[j2], vh0[1], vh0[3]);
                mma_bf16(oacc[2 * nt1],     pal[j2], vh1[0], vh1[2]);
                mma_bf16(oacc[2 * nt1 + 1], pal[j2], vh1[1], vh1[3]);
            }
        }
    }

    const float i0 = 1.0f / l0;
    const float i1 = 1.0f / l1;
    const size_t row0 = ((size_t)b * SEQ + r0g) * HID + h * HDIM;
    const size_t row1 = ((size_t)b * SEQ + r1g) * HID + h * HDIM;
#pragma unroll
    for (int n = 0; n < 16; ++n) {
        const int col = n * 8 + 2 * lam;
        float x0 = oacc[n][0] * i0, x1 = oacc[n][1] * i0;
        float y0 = oacc[n][2] * i1, y1 = oacc[n][3] * i1;
        *(uint32_t*)(attnH + row0 + col) = pk2h(x0, x1);
        *(uint32_t*)(attnH + row1 + col) = pk2h(y0, y1);
        f16 hb;
        hb = __float2half_rn(x0); x0 -= __half2float(hb);
        hb = __float2half_rn(x1); x1 -= __half2float(hb);
        hb = __float2half_rn(y0); y0 -= __half2float(hb);
        hb = __float2half_rn(y1); y1 -= __half2float(hb);
        *(uint32_t*)(attnL + row0 + col) = pk2h(x0, x1);
        *(uint32_t*)(attnL + row1 + col) = pk2h(y0, y1);
    }
}

// ---------------------------------------------------------------------------
extern "C" void kernel_launch(void* const* d_in, const int* in_sizes, int n_in,
                              void* d_out, int out_size)
{
    (void)in_sizes; (void)n_in; (void)out_size;
    const float* hidden = (const float*)d_in[0];
    const float* w_qkv  = (const float*)d_in[1];
    const float* w_o    = (const float*)d_in[2];
    const int*   pos    = (const int*)d_in[3];
    float* out = (float*)d_out;

    f16 *hidH, *hidL, *wqkvt, *wot, *attnH, *attnL;
    bf16 *QH, *QL, *KH, *KL, *VtH, *VtL;
    float *ctab, *stab;
    cudaGetSymbolAddress((void**)&hidH,  g_hidH);
    cudaGetSymbolAddress((void**)&hidL,  g_hidL);
    cudaGetSymbolAddress((void**)&wqkvt, g_wqkvt);
    cudaGetSymbolAddress((void**)&wot,   g_wot);
    cudaGetSymbolAddress((void**)&ctab,  g_ctab);
    cudaGetSymbolAddress((void**)&stab,  g_stab);
    cudaGetSymbolAddress((void**)&QH,    g_QH);
    cudaGetSymbolAddress((void**)&QL,    g_QL);
    cudaGetSymbolAddress((void**)&KH,    g_KH);
    cudaGetSymbolAddress((void**)&KL,    g_KL);
    cudaGetSymbolAddress((void**)&VtH,   g_VtH);
    cudaGetSymbolAddress((void**)&VtL,   g_VtL);
    cudaGetSymbolAddress((void**)&attnH, g_attnH);
    cudaGetSymbolAddress((void**)&attnL, g_attnL);

    // 0) preprocessing
    split_f32h<<<(TOKENS * HID) / 1024, 256>>>(hidden, hidH, hidL);
    transpose_f16<<<dim3(QKVN / 32, HID / 32), dim3(32, 8)>>>(w_qkv, wqkvt, HID, QKVN);
    transpose_f16<<<dim3(HID / 32, HID / 32), dim3(32, 8)>>>(w_o, wot, HID, HID);
    rope_tab<<<(TOKENS * 64) / 256, 256>>>(pos, ctab, stab);

    const int gsmem = NSTG * STG_BYTES;   // 98304 -> 2 CTAs/SM
    cudaFuncSetAttribute(gemm_f16x2, cudaFuncAttributeMaxDynamicSharedMemorySize, gsmem);

    // 1) QKV projection fused with RoPE + head-split + V-transpose (mode 1)
    gemm_f16x2<<<(TOKENS / 128) * (QKVN / 128), 256, gsmem>>>(
        hidH, hidL, wqkvt, nullptr, ctab, stab,
        QH, QL, KH, KL, VtH, VtL,
        TOKENS, QKVN, HID, TOKENS / 128, 1);

    // 2) tensor-core causal flash attention -> fp16-split attn
    cudaFuncSetAttribute(flash_mma, cudaFuncAttributeMaxDynamicSharedMemorySize, ATT_SMEM);
    flash_mma<<<dim3(SEQ / 128, NHEAD, BATCH), 256, ATT_SMEM>>>(
        QH, QL, KH, KL, VtH, VtL, attnH, attnL);

    // 3) output projection (mode 0)
    gemm_f16x2<<<(TOKENS / 128) * (HID / 128), 256, gsmem>>>(
        attnH, attnL, wot, out, nullptr, nullptr,
        nullptr, nullptr, nullptr, nullptr, nullptr, nullptr,
        TOKENS, HID, HID, TOKENS / 128, 0);
}

// round 13
// speedup vs baseline: 1.1921x; 1.0632x over previous
#include <cuda_runtime.h>
#include <cuda_bf16.h>
#include <cuda_fp16.h>
#include <math.h>
#include <stdint.h>

#define BATCH 2
#define SEQ   2048
#define HID   4096
#define NHEAD 32
#define HDIM  128
#define TOKENS (BATCH * SEQ)     // 4096
#define QKVN  (3 * HID)          // 12288
#define HEADS (BATCH * NHEAD)    // 64

typedef __nv_bfloat16 bf16;
typedef __half f16;

// ---------------- scratch (device globals; no allocation allowed) ----------
__device__ f16   g_hidH[(size_t)TOKENS * HID];
__device__ f16   g_hidL[(size_t)TOKENS * HID];
__device__ f16   g_wqkvt[(size_t)QKVN * HID];
__device__ f16   g_wot[(size_t)HID * HID];
__device__ float g_ctab[(size_t)TOKENS * 64];
__device__ float g_stab[(size_t)TOKENS * 64];
__device__ f16   g_QH[(size_t)HEADS * SEQ * HDIM];
__device__ f16   g_QL[(size_t)HEADS * SEQ * HDIM];
__device__ f16   g_KH[(size_t)HEADS * SEQ * HDIM];
__device__ f16   g_VtH[(size_t)HEADS * HDIM * SEQ];
__device__ f16   g_attnH[(size_t)TOKENS * HID];
__device__ f16   g_attnL[(size_t)TOKENS * HID];

// ======================= helpers ==================================
__device__ __forceinline__ uint32_t smem_u32_of(const void* p) {
    uint32_t a;
    asm("{ .reg .u64 t; cvta.to.shared.u64 t, %1; cvt.u32.u64 %0, t; }" : "=r"(a) : "l"(p));
    return a;
}
__device__ __forceinline__ void ldm_x4(uint32_t* r, uint32_t addr) {
    asm volatile("ldmatrix.sync.aligned.m8n8.x4.shared.b16 {%0,%1,%2,%3}, [%4];"
                 : "=r"(r[0]), "=r"(r[1]), "=r"(r[2]), "=r"(r[3]) : "r"(addr));
}
__device__ __forceinline__ void mma_f16(float* d, const uint32_t* a, uint32_t b0, uint32_t b1) {
    asm volatile(
        "mma.sync.aligned.m16n8k16.row.col.f32.f16.f16.f32 "
        "{%0,%1,%2,%3},{%4,%5,%6,%7},{%8,%9},{%0,%1,%2,%3};"
        : "+f"(d[0]), "+f"(d[1]), "+f"(d[2]), "+f"(d[3])
        : "r"(a[0]), "r"(a[1]), "r"(a[2]), "r"(a[3]), "r"(b0), "r"(b1));
}
__device__ __forceinline__ void hsplit(float x, f16& hi, f16& lo) {
    hi = __float2half_rn(x);
    lo = __float2half_rn(x - __half2float(hi));
}
__device__ __forceinline__ uint32_t pk2h(float a, float b) {
    __half2 t = __floats2half2_rn(a, b);
    return *(uint32_t*)&t;
}
__device__ __forceinline__ void cp16(uint32_t smem, const void* g) {
    asm volatile("cp.async.cg.shared.global [%0], [%1], 16;" :: "r"(smem), "l"(g) : "memory");
}
__device__ __forceinline__ void cp_commit() {
    asm volatile("cp.async.commit_group;" ::: "memory");
}
template <int N> __device__ __forceinline__ void cp_wait() {
    asm volatile("cp.async.wait_group %0;" :: "n"(N) : "memory");
}

// ============ fp16 2-term compensated tensor-core GEMM ======================
#define KC  64
#define STG_ARR (128 * KC * 2)       // 16384 B
#define STG_BYTES (3 * STG_ARR)      // 49152 B (Ah, Al, Bh)
#define NSTG 2
#define EPAD 129

__global__ __launch_bounds__(256, 2) void gemm_f16x2(const f16* __restrict__ Ah,
                                                     const f16* __restrict__ Al,
                                                     const f16* __restrict__ Bh,
                                                     float* __restrict__ C,
                                                     const float* __restrict__ ctab,
                                                     const float* __restrict__ stab,
                                                     f16* __restrict__ QH, f16* __restrict__ QL,
                                                     f16* __restrict__ KH, f16* __restrict__ VtH,
                                                     int M, int N, int K, int Mtiles, int mode)
{
    extern __shared__ char gsm[];
    const uint32_t sbase = smem_u32_of(gsm);

    const int tid = threadIdx.x;
    const int warp = tid >> 5, lane = tid & 31;
    const int wm = warp & 3;
    const int wn = warp >> 2;

    const int bx = blockIdx.x;
    const int group = bx / (Mtiles * 8);
    const int rr = bx % (Mtiles * 8);
    const int bm = rr % Mtiles;
    const int bn = group * 8 + rr / Mtiles;

    const f16* Aph = Ah + (size_t)bm * 128 * K;
    const f16* Apl = Al + (size_t)bm * 128 * K;
    const f16* Bph = Bh + (size_t)bn * 128 * K;

    const int lrow = lane & 15;
    const int lc_half = lane >> 4;

    float acc[2][8][4];
#pragma unroll
    for (int t = 0; t < 2; ++t)
#pragma unroll
        for (int n = 0; n < 8; ++n)
#pragma unroll
            for (int i = 0; i < 4; ++i) acc[t][n][i] = 0.f;

    const int nc = K / KC;   // 64
    const int phase = (bx & 3) * (nc >> 2);

    auto issue = [&](int c, int st) {
        const int kc = c * KC;
        const uint32_t sb = sbase + st * STG_BYTES;
#pragma unroll
        for (int q = 0; q < 4; ++q) {
            const int i = tid + q * 256;
            const int row = i >> 3;
            const int chunk = i & 7;
            const int pchunk = chunk ^ (row & 7);
            const uint32_t doff = (uint32_t)(row * 128 + pchunk * 16);
            const size_t soff = (size_t)row * K + kc + chunk * 8;
            cp16(sb + 0 * STG_ARR + doff, Aph + soff);
            cp16(sb + 1 * STG_ARR + doff, Apl + soff);
            cp16(sb + 2 * STG_ARR + doff, Bph + soff);
        }
    };

    issue(phase, 0); cp_commit();

    for (int cc = 0; cc < nc; ++cc) {
        cp_wait<0>();
        __syncthreads();
        if (cc + 1 < nc) {
            int cn = cc + 1 + phase;
            if (cn >= nc) cn -= nc;
            issue(cn, (cc + 1) & 1);
            cp_commit();
        }

        const int st = cc & 1;
        const uint32_t uAh = sbase + st * STG_BYTES;
        const uint32_t uAl = uAh + STG_ARR;
        const uint32_t uBh = uAh + 2 * STG_ARR;

#pragma unroll
        for (int ks = 0; ks < 4; ++ks) {
            const int lc = ks * 2 + lc_half;
            uint32_t ah[2][4], al[2][4];
#pragma unroll
            for (int t = 0; t < 2; ++t) {
                const int ar = wm * 32 + t * 16 + lrow;
                const uint32_t aoff = (uint32_t)(ar * 128 + (lc ^ (ar & 7)) * 16);
                ldm_x4(ah[t], uAh + aoff);
                ldm_x4(al[t], uAl + aoff);
            }
#pragma unroll
            for (int nt = 0; nt < 4; ++nt) {
                const int br = wn * 64 + nt * 16 + lrow;
                const uint32_t boff = (uint32_t)(br * 128 + (lc ^ (br & 7)) * 16);
                uint32_t bh[4];
                ldm_x4(bh, uBh + boff);
                mma_f16(acc[0][2 * nt],     ah[0], bh[0], bh[2]);
                mma_f16(acc[1][2 * nt],     ah[1], bh[0], bh[2]);
                mma_f16(acc[0][2 * nt + 1], ah[0], bh[1], bh[3]);
                mma_f16(acc[1][2 * nt + 1], ah[1], bh[1], bh[3]);
                mma_f16(acc[0][2 * nt],     al[0], bh[0], bh[2]);
                mma_f16(acc[1][2 * nt],     al[1], bh[0], bh[2]);
                mma_f16(acc[0][2 * nt + 1], al[0], bh[1], bh[3]);
                mma_f16(acc[1][2 * nt + 1], al[1], bh[1], bh[3]);
            }
        }
    }

    const int g = lane >> 2;
    const int tc2 = (lane & 3) << 1;

    if (mode == 0) {
#pragma unroll
        for (int t = 0; t < 2; ++t) {
            const int row0 = bm * 128 + wm * 32 + t * 16 + g;
#pragma unroll
            for (int n = 0; n < 8; ++n) {
                const int col = bn * 128 + wn * 64 + n * 8 + tc2;
                *(float2*)(C + (size_t)row0 * N + col) = make_float2(acc[t][n][0], acc[t][n][1]);
                *(float2*)(C + (size_t)(row0 + 8) * N + col) = make_float2(acc[t][n][2], acc[t][n][3]);
            }
        }
        return;
    }

    // -------- fused QKV epilogue ---------------------------------------------
    float* spad = (float*)gsm;
    __syncthreads();
#pragma unroll
    for (int t = 0; t < 2; ++t) {
        const int r0 = wm * 32 + t * 16 + g;
#pragma unroll
        for (int n = 0; n < 8; ++n) {
            const int col = wn * 64 + n * 8 + tc2;
            spad[r0 * EPAD + col]           = acc[t][n][0];
            spad[r0 * EPAD + col + 1]       = acc[t][n][1];
            spad[(r0 + 8) * EPAD + col]     = acc[t][n][2];
            spad[(r0 + 8) * EPAD + col + 1] = acc[t][n][3];
        }
    }
    __syncthreads();

    const int region = bn >> 5;      // 0:Q 1:K 2:V
    const int head = bn & 31;

    if (region == 0) {
        // Q: RoPE + exact 2-limb fp16 split
#pragma unroll
        for (int q = 0; q < 32; ++q) {
            const int p = tid + q * 256;
            const int tok = p >> 6;
            const int i = p & 63;
            const int gtok = bm * 128 + tok;
            const float x1 = spad[tok * EPAD + i];
            const float x2 = spad[tok * EPAD + 64 + i];
            const float cv = ctab[(size_t)gtok * 64 + i];
            const float sv = stab[(size_t)gtok * 64 + i];
            const float r1 = x1 * cv - x2 * sv;
            const float r2 = x2 * cv + x1 * sv;
            const int bb = gtok >> 11;
            const int ss = gtok & 2047;
            const size_t ob = ((size_t)(bb * NHEAD + head) * SEQ + ss) * HDIM;
            f16 hh, ll;
            hsplit(r1, hh, ll); QH[ob + i] = hh;      QL[ob + i] = ll;
            hsplit(r2, hh, ll); QH[ob + 64 + i] = hh; QL[ob + 64 + i] = ll;
        }
    } else if (region == 1) {
        // K: RoPE + single fp16 limb
#pragma unroll
        for (int q = 0; q < 32; ++q) {
            const int p = tid + q * 256;
            const int tok = p >> 6;
            const int i = p & 63;
            const int gtok = bm * 128 + tok;
            const float x1 = spad[tok * EPAD + i];
            const float x2 = spad[tok * EPAD + 64 + i];
            const float cv = ctab[(size_t)gtok * 64 + i];
            const float sv = stab[(size_t)gtok * 64 + i];
            const float r1 = x1 * cv - x2 * sv;
            const float r2 = x2 * cv + x1 * sv;
            const int bb = gtok >> 11;
            const int ss = gtok & 2047;
            const size_t ob = ((size_t)(bb * NHEAD + head) * SEQ + ss) * HDIM;
            KH[ob + i]      = __float2half_rn(r1);
            KH[ob + 64 + i] = __float2half_rn(r2);
        }
    } else {
        // V: transpose + single fp16 limb
#pragma unroll
        for (int q = 0; q < 64; ++q) {
            const int p = tid + q * 256;
            const int tok = p & 127;
            const int d = p >> 7;
            const int gtok = bm * 128 + tok;
            const float v = spad[tok * EPAD + d];
            const int bb = gtok >> 11;
            const int ss = gtok & 2047;
            const size_t od = ((size_t)(bb * NHEAD + head) * HDIM + d) * SEQ + ss;
            VtH[od] = __float2half_rn(v);
        }
    }
}

// ---------------- RoPE cos/sin table (fp64 reduce + fp32 trig) --------------
__global__ __launch_bounds__(256) void rope_tab(const int* __restrict__ pos,
                                                float* __restrict__ ct,
                                                float* __restrict__ st)
{
    const int idx = blockIdx.x * 256 + threadIdx.x;
    const int tok = idx >> 6;
    const int i = idx & 63;
    double inv = exp(-9.210340371976184 * ((double)(2 * i) / 128.0));
    double ang = (double)pos[tok] * inv;
    double r = remainder(ang, 6.283185307179586476925286766559);
    float rf = (float)r;
    ct[idx] = cosf(rf);
    st[idx] = sinf(rf);
}

// ---------------- elementwise split fp32 -> fp16 hi/lo ----------------------
__global__ __launch_bounds__(256) void split_f32h(const float* __restrict__ in,
                                                  f16* __restrict__ hi,
                                                  f16* __restrict__ lo)
{
    const size_t i4 = (size_t)blockIdx.x * 256 + threadIdx.x;
    float4 v = *(const float4*)(in + i4 * 4);
    f16 h[4], l[4];
    hsplit(v.x, h[0], l[0]); hsplit(v.y, h[1], l[1]);
    hsplit(v.z, h[2], l[2]); hsplit(v.w, h[3], l[3]);
    *(uint2*)(hi + i4 * 4) = *(uint2*)h;
    *(uint2*)(lo + i4 * 4) = *(uint2*)l;
}

// ---------------- transpose + round to single fp16 --------------------------
__global__ __launch_bounds__(256) void transpose_f16(const float* __restrict__ in,
                                                     f16* __restrict__ out,
                                                     int R, int Cc)
{
    __shared__ float t[32][33];
    const int c = blockIdx.x * 32 + threadIdx.x;
    const int r0 = blockIdx.y * 32 + threadIdx.y;
#pragma unroll
    for (int i = 0; i < 4; ++i)
        t[threadIdx.y + i * 8][threadIdx.x] = in[(size_t)(r0 + i * 8) * Cc + c];
    __syncthreads();
    const int rc = blockIdx.y * 32 + threadIdx.x;
    const int c0 = blockIdx.x * 32 + threadIdx.y;
#pragma unroll
    for (int i = 0; i < 4; ++i)
        out[(size_t)(c0 + i * 8) * R + rc] = __float2half_rn(t[threadIdx.x][threadIdx.y + i * 8]);
}

// ---------------- tensor-core flash attention (causal, fp16 2-term) ---------
#define QSTR 136
#define VSTR 72
#define oQH 0
#define oQL (oQH + 128 * QSTR * 2)
#define oKH (oQL + 128 * QSTR * 2)                  // 2 bufs, 64*QSTR*2 each
#define oVH (oKH + 2 * 64 * QSTR * 2)               // 2 bufs, 128*VSTR*2 each
#define ATT_SMEM (oVH + 2 * 128 * VSTR * 2)         // 141312 B

__global__ __launch_bounds__(256, 1) void flash_mma(const f16* __restrict__ QHg,
                                                    const f16* __restrict__ QLg,
                                                    const f16* __restrict__ KHg,
                                                    const f16* __restrict__ VtHg,
                                                    f16* __restrict__ attnH,
                                                    f16* __restrict__ attnL)
{
    extern __shared__ char asm_buf[];
    const uint32_t sb = smem_u32_of(asm_buf);

    const int tid = threadIdx.x;
    const int warp = tid >> 5, lane = tid & 31;
    const int g = lane >> 2;
    const int lam = lane & 3;
    const int lrow = lane & 15;
    const int lkh = (lane >> 4) << 3;

    const int qt = (int)(gridDim.x - 1 - blockIdx.x);
    const int h = blockIdx.y;
    const int b = blockIdx.z;
    const int qb = qt * 128;
    const size_t hoff = (size_t)(b * NHEAD + h) * SEQ * HDIM;
    const size_t voff = (size_t)(b * NHEAD + h) * HDIM * SEQ;

#pragma unroll
    for (int j = 0; j < 8; ++j) {
        const int i = tid + j * 256;
        const int row = i >> 4;
        const int seg = (i & 15) << 3;
        const uint32_t doff = (uint32_t)(row * QSTR + seg) * 2;
        const size_t soff = hoff + (size_t)(qb + row) * HDIM + seg;
        cp16(sb + oQH + doff, QHg + soff);
        cp16(sb + oQL + doff, QLg + soff);
    }
    cp_commit();

    const int ktmax = 2 * qt + 1;

    auto issueKV = [&](int kt, int buf) {
        const int kb = kt * 64;
#pragma unroll
        for (int j = 0; j < 4; ++j) {
            const int i = tid + j * 256;
            const int krow = i >> 4;
            const int kseg = (i & 15) << 3;
            const uint32_t kdoff = (uint32_t)(krow * QSTR + kseg) * 2;
            const size_t ksoff = hoff + (size_t)(kb + krow) * HDIM + kseg;
            cp16(sb + oKH + buf * (64 * QSTR * 2) + kdoff, KHg + ksoff);
            const int vrow = i >> 3;
            const int vseg = (i & 7) << 3;
            const uint32_t vdoff = (uint32_t)(vrow * VSTR + vseg) * 2;
            const size_t vsoff = voff + (size_t)vrow * SEQ + kb + vseg;
            cp16(sb + oVH + buf * (128 * VSTR * 2) + vdoff, VtHg + vsoff);
        }
    };

    issueKV(0, 0);
    cp_commit();

    float oacc[16][4];
#pragma unroll
    for (int n = 0; n < 16; ++n)
#pragma unroll
        for (int i = 0; i < 4; ++i) oacc[n][i] = 0.f;
    float m0 = -1e30f, m1 = -1e30f, l0 = 0.f, l1 = 0.f;
    const float scale2 = 0.1275174324f;   // (1/sqrt(128)) * log2(e)

    const int r0g = qb + warp * 16 + g;
    const int r1g = r0g + 8;

    for (int kt = 0; kt <= ktmax; ++kt) {
        const int kb = kt * 64;
        const int buf = kt & 1;

        cp_wait<0>();
        __syncthreads();
        if (kt < ktmax) { issueKV(kt + 1, buf ^ 1); cp_commit(); }

        const uint32_t uQH = sb + oQH, uQL = sb + oQL;
        const uint32_t uKH = sb + oKH + buf * (64 * QSTR * 2);
        const uint32_t uVH = sb + oVH + buf * (128 * VSTR * 2);

        float sacc[8][4];
#pragma unroll
        for (int n = 0; n < 8; ++n)
#pragma unroll
            for (int i = 0; i < 4; ++i) sacc[n][i] = 0.f;

#pragma unroll
        for (int ks = 0; ks < 8; ++ks) {
            uint32_t qh[4], ql[4];
            const uint32_t aoff = (uint32_t)(((warp * 16 + lrow) * QSTR + ks * 16 + lkh) * 2);
            ldm_x4(qh, uQH + aoff);
            ldm_x4(ql, uQL + aoff);
#pragma unroll
            for (int ntp = 0; ntp < 2; ++ntp) {
                const int nt0 = 2 * ntp, nt1 = 2 * ntp + 1;
                uint32_t bh0[4], bh1[4];
                const uint32_t b0off = (uint32_t)(((nt0 * 16 + lrow) * QSTR + ks * 16 + lkh) * 2);
                const uint32_t b1off = (uint32_t)(((nt1 * 16 + lrow) * QSTR + ks * 16 + lkh) * 2);
                ldm_x4(bh0, uKH + b0off);
                ldm_x4(bh1, uKH + b1off);
                mma_f16(sacc[2 * nt0],     qh, bh0[0], bh0[2]);
                mma_f16(sacc[2 * nt0 + 1], qh, bh0[1], bh0[3]);
                mma_f16(sacc[2 * nt1],     qh, bh1[0], bh1[2]);
                mma_f16(sacc[2 * nt1 + 1], qh, bh1[1], bh1[3]);
                mma_f16(sacc[2 * nt0],     ql, bh0[0], bh0[2]);
                mma_f16(sacc[2 * nt0 + 1], ql, bh0[1], bh0[3]);
                mma_f16(sacc[2 * nt1],     ql, bh1[0], bh1[2]);
                mma_f16(sacc[2 * nt1 + 1], ql, bh1[1], bh1[3]);
            }
        }

        const bool need_mask = (kt >= 2 * qt);
        float rm0 = -1e30f, rm1 = -1e30f;
#pragma unroll
        for (int j = 0; j < 8; ++j) {
            const int cg0 = kb + j * 8 + 2 * lam;
#pragma unroll
            for (int i = 0; i < 4; ++i) {
                float v = sacc[j][i] * scale2;
                if (need_mask) {
                    const int cg = cg0 + (i & 1);
                    const int rg = (i < 2) ? r0g : r1g;
                    if (cg > rg) v = -1e30f;
                }
                sacc[j][i] = v;
            }
            rm0 = fmaxf(rm0, fmaxf(sacc[j][0], sacc[j][1]));
            rm1 = fmaxf(rm1, fmaxf(sacc[j][2], sacc[j][3]));
        }
#pragma unroll
        for (int off = 1; off <= 2; off <<= 1) {
            rm0 = fmaxf(rm0, __shfl_xor_sync(0xffffffffu, rm0, off));
            rm1 = fmaxf(rm1, __shfl_xor_sync(0xffffffffu, rm1, off));
        }
        const float mn0 = fmaxf(m0, rm0);
        const float mn1 = fmaxf(m1, rm1);
        const float al0 = exp2f(m0 - mn0);
        const float al1 = exp2f(m1 - mn1);
        m0 = mn0; m1 = mn1;

        float rs0 = 0.f, rs1 = 0.f;
#pragma unroll
        for (int j = 0; j < 8; ++j) {
            sacc[j][0] = exp2f(sacc[j][0] - mn0);
            sacc[j][1] = exp2f(sacc[j][1] - mn0);
            sacc[j][2] = exp2f(sacc[j][2] - mn1);
            sacc[j][3] = exp2f(sacc[j][3] - mn1);
            rs0 += sacc[j][0] + sacc[j][1];
            rs1 += sacc[j][2] + sacc[j][3];
        }
#pragma unroll
        for (int off = 1; off <= 2; off <<= 1) {
            rs0 += __shfl_xor_sync(0xffffffffu, rs0, off);
            rs1 += __shfl_xor_sync(0xffffffffu, rs1, off);
        }
        l0 = l0 * al0 + rs0;
        l1 = l1 * al1 + rs1;

#pragma unroll
        for (int n = 0; n < 16; ++n) {
            oacc[n][0] *= al0; oacc[n][1] *= al0;
            oacc[n][2] *= al1; oacc[n][3] *= al1;
        }

        // pack P: exact 2-limb fp16
        uint32_t pah[4][4], pal[4][4];
#pragma unroll
        for (int j2 = 0; j2 < 4; ++j2) {
            float p00 = sacc[2 * j2][0],     p01 = sacc[2 * j2][1];
            float p02 = sacc[2 * j2][2],     p03 = sacc[2 * j2][3];
            float p10 = sacc[2 * j2 + 1][0], p11 = sacc[2 * j2 + 1][1];
            float p12 = sacc[2 * j2 + 1][2], p13 = sacc[2 * j2 + 1][3];
            pah[j2][0] = pk2h(p00, p01);
            pah[j2][1] = pk2h(p02, p03);
            pah[j2][2] = pk2h(p10, p11);
            pah[j2][3] = pk2h(p12, p13);
            f16 hh;
            hh = __float2half_rn(p00); p00 -= __half2float(hh);
            hh = __float2half_rn(p01); p01 -= __half2float(hh);
            hh = __float2half_rn(p02); p02 -= __half2float(hh);
            hh = __float2half_rn(p03); p03 -= __half2float(hh);
            hh = __float2half_rn(p10); p10 -= __half2float(hh);
            hh = __float2half_rn(p11); p11 -= __half2float(hh);
            hh = __float2half_rn(p12); p12 -= __half2float(hh);
            hh = __float2half_rn(p13); p13 -= __half2float(hh);
            pal[j2][0] = pk2h(p00, p01);
            pal[j2][1] = pk2h(p02, p03);
            pal[j2][2] = pk2h(p10, p11);
            pal[j2][3] = pk2h(p12, p13);
        }

#pragma unroll
        for (int ntp = 0; ntp < 4; ++ntp) {
            const int nt0 = 2 * ntp, nt1 = 2 * ntp + 1;
#pragma unroll
            for (int j2 = 0; j2 < 4; ++j2) {
                uint32_t vh0[4], vh1[4];
                const uint32_t v0off = (uint32_t)(((nt0 * 16 + lrow) * VSTR + j2 * 16 + lkh) * 2);
                const uint32_t v1off = (uint32_t)(((nt1 * 16 + lrow) * VSTR + j2 * 16 + lkh) * 2);
                ldm_x4(vh0, uVH + v0off);
                ldm_x4(vh1, uVH + v1off);
                mma_f16(oacc[2 * nt0],     pah[j2], vh0[0], vh0[2]);
                mma_f16(oacc[2 * nt0 + 1], pah[j2], vh0[1], vh0[3]);
                mma_f16(oacc[2 * nt1],     pah[j2], vh1[0], vh1[2]);
                mma_f16(oacc[2 * nt1 + 1], pah[j2], vh1[1], vh1[3]);
                mma_f16(oacc[2 * nt0],     pal[j2], vh0[0], vh0[2]);
                mma_f16(oacc[2 * nt0 + 1], pal[j2], vh0[1], vh0[3]);
                mma_f16(oacc[2 * nt1],     pal[j2], vh1[0], vh1[2]);
                mma_f16(oacc[2 * nt1 + 1], pal[j2], vh1[1], vh1[3]);
            }
        }
    }

    // epilogue: normalize, split to fp16 hi/lo for the O-proj
    const float i0 = 1.0f / l0;
    const float i1 = 1.0f / l1;
    const size_t row0 = ((size_t)b * SEQ + r0g) * HID + h * HDIM;
    const size_t row1 = ((size_t)b * SEQ + r1g) * HID + h * HDIM;
#pragma unroll
    for (int n = 0; n < 16; ++n) {
        const int col = n * 8 + 2 * lam;
        float x0 = oacc[n][0] * i0, x1 = oacc[n][1] * i0;
        float y0 = oacc[n][2] * i1, y1 = oacc[n][3] * i1;
        *(uint32_t*)(attnH + row0 + col) = pk2h(x0, x1);
        *(uint32_t*)(attnH + row1 + col) = pk2h(y0, y1);
        f16 hb;
        hb = __float2half_rn(x0); x0 -= __half2float(hb);
        hb = __float2half_rn(x1); x1 -= __half2float(hb);
        hb = __float2half_rn(y0); y0 -= __half2float(hb);
        hb = __float2half_rn(y1); y1 -= __half2float(hb);
        *(uint32_t*)(attnL + row0 + col) = pk2h(x0, x1);
        *(uint32_t*)(attnL + row1 + col) = pk2h(y0, y1);
    }
}

// ---------------------------------------------------------------------------
extern "C" void kernel_launch(void* const* d_in, const int* in_sizes, int n_in,
                              void* d_out, int out_size)
{
    (void)in_sizes; (void)n_in; (void)out_size;
    const float* hidden = (const float*)d_in[0];
    const float* w_qkv  = (const float*)d_in[1];
    const float* w_o    = (const float*)d_in[2];
    const int*   pos    = (const int*)d_in[3];
    float* out = (float*)d_out;

    f16 *hidH, *hidL, *wqkvt, *wot, *attnH, *attnL;
    f16 *QH, *QL, *KH, *VtH;
    float *ctab, *stab;
    cudaGetSymbolAddress((void**)&hidH,  g_hidH);
    cudaGetSymbolAddress((void**)&hidL,  g_hidL);
    cudaGetSymbolAddress((void**)&wqkvt, g_wqkvt);
    cudaGetSymbolAddress((void**)&wot,   g_wot);
    cudaGetSymbolAddress((void**)&ctab,  g_ctab);
    cudaGetSymbolAddress((void**)&stab,  g_stab);
    cudaGetSymbolAddress((void**)&QH,    g_QH);
    cudaGetSymbolAddress((void**)&QL,    g_QL);
    cudaGetSymbolAddress((void**)&KH,    g_KH);
    cudaGetSymbolAddress((void**)&VtH,   g_VtH);
    cudaGetSymbolAddress((void**)&attnH, g_attnH);
    cudaGetSymbolAddress((void**)&attnL, g_attnL);

    // 0) preprocessing
    split_f32h<<<(TOKENS * HID) / 1024, 256>>>(hidden, hidH, hidL);
    transpose_f16<<<dim3(QKVN / 32, HID / 32), dim3(32, 8)>>>(w_qkv, wqkvt, HID, QKVN);
    transpose_f16<<<dim3(HID / 32, HID / 32), dim3(32, 8)>>>(w_o, wot, HID, HID);
    rope_tab<<<(TOKENS * 64) / 256, 256>>>(pos, ctab, stab);

    const int gsmem = NSTG * STG_BYTES;   // 98304 -> 2 CTAs/SM
    cudaFuncSetAttribute(gemm_f16x2, cudaFuncAttributeMaxDynamicSharedMemorySize, gsmem);

    // 1) QKV projection fused with RoPE + head-split + V-transpose (mode 1)
    gemm_f16x2<<<(TOKENS / 128) * (QKVN / 128), 256, gsmem>>>(
        hidH, hidL, wqkvt, nullptr, ctab, stab,
        QH, QL, KH, VtH,
        TOKENS, QKVN, HID, TOKENS / 128, 1);

    // 2) tensor-core causal flash attention (fp16 2-term) -> fp16-split attn
    cudaFuncSetAttribute(flash_mma, cudaFuncAttributeMaxDynamicSharedMemorySize, ATT_SMEM);
    flash_mma<<<dim3(SEQ / 128, NHEAD, BATCH), 256, ATT_SMEM>>>(
        QH, QL, KH, VtH, attnH, attnL);

    // 3) output projection (mode 0)
    gemm_f16x2<<<(TOKENS / 128) * (HID / 128), 256, gsmem>>>(
        attnH, attnL, wot, out, nullptr, nullptr,
        nullptr, nullptr, nullptr, nullptr,
        TOKENS, HID, HID, TOKENS / 128, 0);
}

// round 14
// speedup vs baseline: 1.3163x; 1.1042x over previous
#include <cuda_runtime.h>
#include <cuda_bf16.h>
#include <cuda_fp16.h>
#include <math.h>
#include <stdint.h>

#define BATCH 2
#define SEQ   2048
#define HID   4096
#define NHEAD 32
#define HDIM  128
#define TOKENS (BATCH * SEQ)     // 4096
#define QKVN  (3 * HID)          // 12288
#define HEADS (BATCH * NHEAD)    // 64

typedef __half f16;

// ---------------- scratch (device globals; no allocation allowed) ----------
__device__ f16   g_hidH[(size_t)TOKENS * HID];
__device__ f16   g_hidL[(size_t)TOKENS * HID];
__device__ f16   g_wqkvt[(size_t)QKVN * HID];
__device__ f16   g_wot[(size_t)HID * HID];
__device__ float g_ctab[(size_t)TOKENS * 64];
__device__ float g_stab[(size_t)TOKENS * 64];
__device__ f16   g_QH[(size_t)HEADS * SEQ * HDIM];
__device__ f16   g_QL[(size_t)HEADS * SEQ * HDIM];
__device__ f16   g_KH[(size_t)HEADS * SEQ * HDIM];
__device__ f16   g_VtH[(size_t)HEADS * HDIM * SEQ];
__device__ f16   g_attnH[(size_t)TOKENS * HID];

// ======================= helpers ==================================
__device__ __forceinline__ uint32_t smem_u32_of(const void* p) {
    uint32_t a;
    asm("{ .reg .u64 t; cvta.to.shared.u64 t, %1; cvt.u32.u64 %0, t; }" : "=r"(a) : "l"(p));
    return a;
}
__device__ __forceinline__ void ldm_x4(uint32_t* r, uint32_t addr) {
    asm volatile("ldmatrix.sync.aligned.m8n8.x4.shared.b16 {%0,%1,%2,%3}, [%4];"
                 : "=r"(r[0]), "=r"(r[1]), "=r"(r[2]), "=r"(r[3]) : "r"(addr));
}
__device__ __forceinline__ void mma_f16(float* d, const uint32_t* a, uint32_t b0, uint32_t b1) {
    asm volatile(
        "mma.sync.aligned.m16n8k16.row.col.f32.f16.f16.f32 "
        "{%0,%1,%2,%3},{%4,%5,%6,%7},{%8,%9},{%0,%1,%2,%3};"
        : "+f"(d[0]), "+f"(d[1]), "+f"(d[2]), "+f"(d[3])
        : "r"(a[0]), "r"(a[1]), "r"(a[2]), "r"(a[3]), "r"(b0), "r"(b1));
}
__device__ __forceinline__ void hsplit(float x, f16& hi, f16& lo) {
    hi = __float2half_rn(x);
    lo = __float2half_rn(x - __half2float(hi));
}
__device__ __forceinline__ uint32_t pk2h(float a, float b) {
    __half2 t = __floats2half2_rn(a, b);
    return *(uint32_t*)&t;
}
__device__ __forceinline__ void cp16(uint32_t smem, const void* g) {
    asm volatile("cp.async.cg.shared.global [%0], [%1], 16;" :: "r"(smem), "l"(g) : "memory");
}
__device__ __forceinline__ void cp_commit() {
    asm volatile("cp.async.commit_group;" ::: "memory");
}
template <int N> __device__ __forceinline__ void cp_wait() {
    asm volatile("cp.async.wait_group %0;" :: "n"(N) : "memory");
}

// ============ fp16 2-term compensated GEMM (QKV, fused epilogue) ============
#define KC  64
#define STG_ARR (128 * KC * 2)       // 16384 B
#define STG_BYTES (3 * STG_ARR)      // 49152 B (Ah, Al, Bh)
#define NSTG 2
#define EPAD 129

__global__ __launch_bounds__(256, 2) void gemm_qkv(const f16* __restrict__ Ah,
                                                   const f16* __restrict__ Al,
                                                   const f16* __restrict__ Bh,
                                                   const float* __restrict__ ctab,
                                                   const float* __restrict__ stab,
                                                   f16* __restrict__ QH, f16* __restrict__ QL,
                                                   f16* __restrict__ KH, f16* __restrict__ VtH,
                                                   int K, int Mtiles)
{
    extern __shared__ char gsm[];
    const uint32_t sbase = smem_u32_of(gsm);

    const int tid = threadIdx.x;
    const int warp = tid >> 5, lane = tid & 31;
    const int wm = warp & 3;
    const int wn = warp >> 2;

    const int bx = blockIdx.x;
    const int group = bx / (Mtiles * 8);
    const int rr = bx % (Mtiles * 8);
    const int bm = rr % Mtiles;
    const int bn = group * 8 + rr / Mtiles;

    const f16* Aph = Ah + (size_t)bm * 128 * K;
    const f16* Apl = Al + (size_t)bm * 128 * K;
    const f16* Bph = Bh + (size_t)bn * 128 * K;

    const int lrow = lane & 15;
    const int lc_half = lane >> 4;

    float acc[2][8][4];
#pragma unroll
    for (int t = 0; t < 2; ++t)
#pragma unroll
        for (int n = 0; n < 8; ++n)
#pragma unroll
            for (int i = 0; i < 4; ++i) acc[t][n][i] = 0.f;

    const int nc = K / KC;   // 64
    const int phase = (bx & 3) * (nc >> 2);

    auto issue = [&](int c, int st) {
        const int kc = c * KC;
        const uint32_t sb = sbase + st * STG_BYTES;
#pragma unroll
        for (int q = 0; q < 4; ++q) {
            const int i = tid + q * 256;
            const int row = i >> 3;
            const int chunk = i & 7;
            const int pchunk = chunk ^ (row & 7);
            const uint32_t doff = (uint32_t)(row * 128 + pchunk * 16);
            const size_t soff = (size_t)row * K + kc + chunk * 8;
            cp16(sb + 0 * STG_ARR + doff, Aph + soff);
            cp16(sb + 1 * STG_ARR + doff, Apl + soff);
            cp16(sb + 2 * STG_ARR + doff, Bph + soff);
        }
    };

    issue(phase, 0); cp_commit();

    for (int cc = 0; cc < nc; ++cc) {
        cp_wait<0>();
        __syncthreads();
        if (cc + 1 < nc) {
            int cn = cc + 1 + phase;
            if (cn >= nc) cn -= nc;
            issue(cn, (cc + 1) & 1);
            cp_commit();
        }

        const int st = cc & 1;
        const uint32_t uAh = sbase + st * STG_BYTES;
        const uint32_t uAl = uAh + STG_ARR;
        const uint32_t uBh = uAh + 2 * STG_ARR;

#pragma unroll
        for (int ks = 0; ks < 4; ++ks) {
            const int lc = ks * 2 + lc_half;
            uint32_t ah[2][4], al[2][4];
#pragma unroll
            for (int t = 0; t < 2; ++t) {
                const int ar = wm * 32 + t * 16 + lrow;
                const uint32_t aoff = (uint32_t)(ar * 128 + (lc ^ (ar & 7)) * 16);
                ldm_x4(ah[t], uAh + aoff);
                ldm_x4(al[t], uAl + aoff);
            }
#pragma unroll
            for (int nt = 0; nt < 4; ++nt) {
                const int br = wn * 64 + nt * 16 + lrow;
                const uint32_t boff = (uint32_t)(br * 128 + (lc ^ (br & 7)) * 16);
                uint32_t bh[4];
                ldm_x4(bh, uBh + boff);
                mma_f16(acc[0][2 * nt],     ah[0], bh[0], bh[2]);
                mma_f16(acc[1][2 * nt],     ah[1], bh[0], bh[2]);
                mma_f16(acc[0][2 * nt + 1], ah[0], bh[1], bh[3]);
                mma_f16(acc[1][2 * nt + 1], ah[1], bh[1], bh[3]);
                mma_f16(acc[0][2 * nt],     al[0], bh[0], bh[2]);
                mma_f16(acc[1][2 * nt],     al[1], bh[0], bh[2]);
                mma_f16(acc[0][2 * nt + 1], al[0], bh[1], bh[3]);
                mma_f16(acc[1][2 * nt + 1], al[1], bh[1], bh[3]);
            }
        }
    }

    const int g = lane >> 2;
    const int tc2 = (lane & 3) << 1;

    // -------- fused QKV epilogue ---------------------------------------------
    float* spad = (float*)gsm;
    __syncthreads();
#pragma unroll
    for (int t = 0; t < 2; ++t) {
        const int r0 = wm * 32 + t * 16 + g;
#pragma unroll
        for (int n = 0; n < 8; ++n) {
            const int col = wn * 64 + n * 8 + tc2;
            spad[r0 * EPAD + col]           = acc[t][n][0];
            spad[r0 * EPAD + col + 1]       = acc[t][n][1];
            spad[(r0 + 8) * EPAD + col]     = acc[t][n][2];
            spad[(r0 + 8) * EPAD + col + 1] = acc[t][n][3];
        }
    }
    __syncthreads();

    const int region = bn >> 5;      // 0:Q 1:K 2:V
    const int head = bn & 31;

    if (region == 0) {
#pragma unroll
        for (int q = 0; q < 32; ++q) {
            const int p = tid + q * 256;
            const int tok = p >> 6;
            const int i = p & 63;
            const int gtok = bm * 128 + tok;
            const float x1 = spad[tok * EPAD + i];
            const float x2 = spad[tok * EPAD + 64 + i];
            const float cv = ctab[(size_t)gtok * 64 + i];
            const float sv = stab[(size_t)gtok * 64 + i];
            const float r1 = x1 * cv - x2 * sv;
            const float r2 = x2 * cv + x1 * sv;
            const int bb = gtok >> 11;
            const int ss = gtok & 2047;
            const size_t ob = ((size_t)(bb * NHEAD + head) * SEQ + ss) * HDIM;
            f16 hh, ll;
            hsplit(r1, hh, ll); QH[ob + i] = hh;      QL[ob + i] = ll;
            hsplit(r2, hh, ll); QH[ob + 64 + i] = hh; QL[ob + 64 + i] = ll;
        }
    } else if (region == 1) {
#pragma unroll
        for (int q = 0; q < 32; ++q) {
            const int p = tid + q * 256;
            const int tok = p >> 6;
            const int i = p & 63;
            const int gtok = bm * 128 + tok;
            const float x1 = spad[tok * EPAD + i];
            const float x2 = spad[tok * EPAD + 64 + i];
            const float cv = ctab[(size_t)gtok * 64 + i];
            const float sv = stab[(size_t)gtok * 64 + i];
            const float r1 = x1 * cv - x2 * sv;
            const float r2 = x2 * cv + x1 * sv;
            const int bb = gtok >> 11;
            const int ss = gtok & 2047;
            const size_t ob = ((size_t)(bb * NHEAD + head) * SEQ + ss) * HDIM;
            KH[ob + i]      = __float2half_rn(r1);
            KH[ob + 64 + i] = __float2half_rn(r2);
        }
    } else {
#pragma unroll
        for (int q = 0; q < 64; ++q) {
            const int p = tid + q * 256;
            const int tok = p & 127;
            const int d = p >> 7;
            const int gtok = bm * 128 + tok;
            const float v = spad[tok * EPAD + d];
            const int bb = gtok >> 11;
            const int ss = gtok & 2047;
            const size_t od = ((size_t)(bb * NHEAD + head) * HDIM + d) * SEQ + ss;
            VtH[od] = __float2half_rn(v);
        }
    }
}

// ============ fp16 single-term GEMM (O-projection) ==========================
#define STG1_BYTES (2 * STG_ARR)     // 32768 B (Ah, Bh)

__global__ __launch_bounds__(256, 2) void gemm_oproj(const f16* __restrict__ Ah,
                                                     const f16* __restrict__ Bh,
                                                     float* __restrict__ C,
                                                     int N, int K, int Mtiles)
{
    extern __shared__ char gsm[];
    const uint32_t sbase = smem_u32_of(gsm);

    const int tid = threadIdx.x;
    const int warp = tid >> 5, lane = tid & 31;
    const int wm = warp & 3;
    const int wn = warp >> 2;

    const int bx = blockIdx.x;
    const int group = bx / (Mtiles * 8);
    const int rr = bx % (Mtiles * 8);
    const int bm = rr % Mtiles;
    const int bn = group * 8 + rr / Mtiles;

    const f16* Aph = Ah + (size_t)bm * 128 * K;
    const f16* Bph = Bh + (size_t)bn * 128 * K;

    const int lrow = lane & 15;
    const int lc_half = lane >> 4;

    float acc[2][8][4];
#pragma unroll
    for (int t = 0; t < 2; ++t)
#pragma unroll
        for (int n = 0; n < 8; ++n)
#pragma unroll
            for (int i = 0; i < 4; ++i) acc[t][n][i] = 0.f;

    const int nc = K / KC;   // 64
    const int phase = (bx & 3) * (nc >> 2);

    auto issue = [&](int c, int st) {
        const int kc = c * KC;
        const uint32_t sb = sbase + st * STG1_BYTES;
#pragma unroll
        for (int q = 0; q < 4; ++q) {
            const int i = tid + q * 256;
            const int row = i >> 3;
            const int chunk = i & 7;
            const int pchunk = chunk ^ (row & 7);
            const uint32_t doff = (uint32_t)(row * 128 + pchunk * 16);
            const size_t soff = (size_t)row * K + kc + chunk * 8;
            cp16(sb + doff, Aph + soff);
            cp16(sb + STG_ARR + doff, Bph + soff);
        }
    };

    issue(phase, 0); cp_commit();

    for (int cc = 0; cc < nc; ++cc) {
        cp_wait<0>();
        __syncthreads();
        if (cc + 1 < nc) {
            int cn = cc + 1 + phase;
            if (cn >= nc) cn -= nc;
            issue(cn, (cc + 1) & 1);
            cp_commit();
        }

        const int st = cc & 1;
        const uint32_t uAh = sbase + st * STG1_BYTES;
        const uint32_t uBh = uAh + STG_ARR;

#pragma unroll
        for (int ks = 0; ks < 4; ++ks) {
            const int lc = ks * 2 + lc_half;
            uint32_t ah[2][4];
#pragma unroll
            for (int t = 0; t < 2; ++t) {
                const int ar = wm * 32 + t * 16 + lrow;
                const uint32_t aoff = (uint32_t)(ar * 128 + (lc ^ (ar & 7)) * 16);
                ldm_x4(ah[t], uAh + aoff);
            }
#pragma unroll
            for (int nt = 0; nt < 4; ++nt) {
                const int br = wn * 64 + nt * 16 + lrow;
                const uint32_t boff = (uint32_t)(br * 128 + (lc ^ (br & 7)) * 16);
                uint32_t bh[4];
                ldm_x4(bh, uBh + boff);
                mma_f16(acc[0][2 * nt],     ah[0], bh[0], bh[2]);
                mma_f16(acc[1][2 * nt],     ah[1], bh[0], bh[2]);
                mma_f16(acc[0][2 * nt + 1], ah[0], bh[1], bh[3]);
                mma_f16(acc[1][2 * nt + 1], ah[1], bh[1], bh[3]);
            }
        }
    }

    const int g = lane >> 2;
    const int tc2 = (lane & 3) << 1;
#pragma unroll
    for (int t = 0; t < 2; ++t) {
        const int row0 = bm * 128 + wm * 32 + t * 16 + g;
#pragma unroll
        for (int n = 0; n < 8; ++n) {
            const int col = bn * 128 + wn * 64 + n * 8 + tc2;
            *(float2*)(C + (size_t)row0 * N + col) = make_float2(acc[t][n][0], acc[t][n][1]);
            *(float2*)(C + (size_t)(row0 + 8) * N + col) = make_float2(acc[t][n][2], acc[t][n][3]);
        }
    }
}

// ---------------- RoPE cos/sin table (fp64 reduce + fp32 trig) --------------
__global__ __launch_bounds__(256) void rope_tab(const int* __restrict__ pos,
                                                float* __restrict__ ct,
                                                float* __restrict__ st)
{
    const int idx = blockIdx.x * 256 + threadIdx.x;
    const int tok = idx >> 6;
    const int i = idx & 63;
    double inv = exp(-9.210340371976184 * ((double)(2 * i) / 128.0));
    double ang = (double)pos[tok] * inv;
    double r = remainder(ang, 6.283185307179586476925286766559);
    float rf = (float)r;
    ct[idx] = cosf(rf);
    st[idx] = sinf(rf);
}

// ---------------- elementwise split fp32 -> fp16 hi/lo ----------------------
__global__ __launch_bounds__(256) void split_f32h(const float* __restrict__ in,
                                                  f16* __restrict__ hi,
                                                  f16* __restrict__ lo)
{
    const size_t i4 = (size_t)blockIdx.x * 256 + threadIdx.x;
    float4 v = *(const float4*)(in + i4 * 4);
    f16 h[4], l[4];
    hsplit(v.x, h[0], l[0]); hsplit(v.y, h[1], l[1]);
    hsplit(v.z, h[2], l[2]); hsplit(v.w, h[3], l[3]);
    *(uint2*)(hi + i4 * 4) = *(uint2*)h;
    *(uint2*)(lo + i4 * 4) = *(uint2*)l;
}

// ---------------- transpose + round to single fp16 --------------------------
__global__ __launch_bounds__(256) void transpose_f16(const float* __restrict__ in,
                                                     f16* __restrict__ out,
                                                     int R, int Cc)
{
    __shared__ float t[32][33];
    const int c = blockIdx.x * 32 + threadIdx.x;
    const int r0 = blockIdx.y * 32 + threadIdx.y;
#pragma unroll
    for (int i = 0; i < 4; ++i)
        t[threadIdx.y + i * 8][threadIdx.x] = in[(size_t)(r0 + i * 8) * Cc + c];
    __syncthreads();
    const int rc = blockIdx.y * 32 + threadIdx.x;
    const int c0 = blockIdx.x * 32 + threadIdx.y;
#pragma unroll
    for (int i = 0; i < 4; ++i)
        out[(size_t)(c0 + i * 8) * R + rc] = __float2half_rn(t[threadIdx.x][threadIdx.y + i * 8]);
}

// ---------------- tensor-core flash attention (causal, fp16 2-term) ---------
#define QSTR 136
#define VSTR 72
#define oQH 0
#define oQL (oQH + 128 * QSTR * 2)
#define oKH (oQL + 128 * QSTR * 2)
#define oVH (oKH + 2 * 64 * QSTR * 2)
#define ATT_SMEM (oVH + 2 * 128 * VSTR * 2)

__global__ __launch_bounds__(256, 1) void flash_mma(const f16* __restrict__ QHg,
                                                    const f16* __restrict__ QLg,
                                                    const f16* __restrict__ KHg,
                                                    const f16* __restrict__ VtHg,
                                                    f16* __restrict__ attnH)
{
    extern __shared__ char asm_buf[];
    const uint32_t sb = smem_u32_of(asm_buf);

    const int tid = threadIdx.x;
    const int warp = tid >> 5, lane = tid & 31;
    const int g = lane >> 2;
    const int lam = lane & 3;
    const int lrow = lane & 15;
    const int lkh = (lane >> 4) << 3;

    const int qt = (int)(gridDim.x - 1 - blockIdx.x);
    const int h = blockIdx.y;
    const int b = blockIdx.z;
    const int qb = qt * 128;
    const size_t hoff = (size_t)(b * NHEAD + h) * SEQ * HDIM;
    const size_t voff = (size_t)(b * NHEAD + h) * HDIM * SEQ;

#pragma unroll
    for (int j = 0; j < 8; ++j) {
        const int i = tid + j * 256;
        const int row = i >> 4;
        const int seg = (i & 15) << 3;
        const uint32_t doff = (uint32_t)(row * QSTR + seg) * 2;
        const size_t soff = hoff + (size_t)(qb + row) * HDIM + seg;
        cp16(sb + oQH + doff, QHg + soff);
        cp16(sb + oQL + doff, QLg + soff);
    }
    cp_commit();

    const int ktmax = 2 * qt + 1;

    auto issueKV = [&](int kt, int buf) {
        const int kb = kt * 64;
#pragma unroll
        for (int j = 0; j < 4; ++j) {
            const int i = tid + j * 256;
            const int krow = i >> 4;
            const int kseg = (i & 15) << 3;
            const uint32_t kdoff = (uint32_t)(krow * QSTR + kseg) * 2;
            const size_t ksoff = hoff + (size_t)(kb + krow) * HDIM + kseg;
            cp16(sb + oKH + buf * (64 * QSTR * 2) + kdoff, KHg + ksoff);
            const int vrow = i >> 3;
            const int vseg = (i & 7) << 3;
            const uint32_t vdoff = (uint32_t)(vrow * VSTR + vseg) * 2;
            const size_t vsoff = voff + (size_t)vrow * SEQ + kb + vseg;
            cp16(sb + oVH + buf * (128 * VSTR * 2) + vdoff, VtHg + vsoff);
        }
    };

    issueKV(0, 0);
    cp_commit();

    float oacc[16][4];
#pragma unroll
    for (int n = 0; n < 16; ++n)
#pragma unroll
        for (int i = 0; i < 4; ++i) oacc[n][i] = 0.f;
    float m0 = -1e30f, m1 = -1e30f, l0 = 0.f, l1 = 0.f;
    const float scale2 = 0.1275174324f;   // (1/sqrt(128)) * log2(e)

    const int r0g = qb + warp * 16 + g;
    const int r1g = r0g + 8;

    for (int kt = 0; kt <= ktmax; ++kt) {
        const int kb = kt * 64;
        const int buf = kt & 1;

        cp_wait<0>();
        __syncthreads();
        if (kt < ktmax) { issueKV(kt + 1, buf ^ 1); cp_commit(); }

        const uint32_t uQH = sb + oQH, uQL = sb + oQL;
        const uint32_t uKH = sb + oKH + buf * (64 * QSTR * 2);
        const uint32_t uVH = sb + oVH + buf * (128 * VSTR * 2);

        float sacc[8][4];
#pragma unroll
        for (int n = 0; n < 8; ++n)
#pragma unroll
            for (int i = 0; i < 4; ++i) sacc[n][i] = 0.f;

#pragma unroll
        for (int ks = 0; ks < 8; ++ks) {
            uint32_t qh[4], ql[4];
            const uint32_t aoff = (uint32_t)(((warp * 16 + lrow) * QSTR + ks * 16 + lkh) * 2);
            ldm_x4(qh, uQH + aoff);
            ldm_x4(ql, uQL + aoff);
#pragma unroll
            for (int ntp = 0; ntp < 2; ++ntp) {
                const int nt0 = 2 * ntp, nt1 = 2 * ntp + 1;
                uint32_t bh0[4], bh1[4];
                const uint32_t b0off = (uint32_t)(((nt0 * 16 + lrow) * QSTR + ks * 16 + lkh) * 2);
                const uint32_t b1off = (uint32_t)(((nt1 * 16 + lrow) * QSTR + ks * 16 + lkh) * 2);
                ldm_x4(bh0, uKH + b0off);
                ldm_x4(bh1, uKH + b1off);
                mma_f16(sacc[2 * nt0],     qh, bh0[0], bh0[2]);
                mma_f16(sacc[2 * nt0 + 1], qh, bh0[1], bh0[3]);
                mma_f16(sacc[2 * nt1],     qh, bh1[0], bh1[2]);
                mma_f16(sacc[2 * nt1 + 1], qh, bh1[1], bh1[3]);
                mma_f16(sacc[2 * nt0],     ql, bh0[0], bh0[2]);
                mma_f16(sacc[2 * nt0 + 1], ql, bh0[1], bh0[3]);
                mma_f16(sacc[2 * nt1],     ql, bh1[0], bh1[2]);
                mma_f16(sacc[2 * nt1 + 1], ql, bh1[1], bh1[3]);
            }
        }

        const bool need_mask = (kt >= 2 * qt);
        float rm0 = -1e30f, rm1 = -1e30f;
#pragma unroll
        for (int j = 0; j < 8; ++j) {
            const int cg0 = kb + j * 8 + 2 * lam;
#pragma unroll
            for (int i = 0; i < 4; ++i) {
                float v = sacc[j][i] * scale2;
                if (need_mask) {
                    const int cg = cg0 + (i & 1);
                    const int rg = (i < 2) ? r0g : r1g;
                    if (cg > rg) v = -1e30f;
                }
                sacc[j][i] = v;
            }
            rm0 = fmaxf(rm0, fmaxf(sacc[j][0], sacc[j][1]));
            rm1 = fmaxf(rm1, fmaxf(sacc[j][2], sacc[j][3]));
        }
#pragma unroll
        for (int off = 1; off <= 2; off <<= 1) {
            rm0 = fmaxf(rm0, __shfl_xor_sync(0xffffffffu, rm0, off));
            rm1 = fmaxf(rm1, __shfl_xor_sync(0xffffffffu, rm1, off));
        }
        const float mn0 = fmaxf(m0, rm0);
        const float mn1 = fmaxf(m1, rm1);
        const float al0 = exp2f(m0 - mn0);
        const float al1 = exp2f(m1 - mn1);
        m0 = mn0; m1 = mn1;

        float rs0 = 0.f, rs1 = 0.f;
#pragma unroll
        for (int j = 0; j < 8; ++j) {
            sacc[j][0] = exp2f(sacc[j][0] - mn0);
            sacc[j][1] = exp2f(sacc[j][1] - mn0);
            sacc[j][2] = exp2f(sacc[j][2] - mn1);
            sacc[j][3] = exp2f(sacc[j][3] - mn1);
            rs0 += sacc[j][0] + sacc[j][1];
            rs1 += sacc[j][2] + sacc[j][3];
        }
#pragma unroll
        for (int off = 1; off <= 2; off <<= 1) {
            rs0 += __shfl_xor_sync(0xffffffffu, rs0, off);
            rs1 += __shfl_xor_sync(0xffffffffu, rs1, off);
        }
        l0 = l0 * al0 + rs0;
        l1 = l1 * al1 + rs1;

#pragma unroll
        for (int n = 0; n < 16; ++n) {
            oacc[n][0] *= al0; oacc[n][1] *= al0;
            oacc[n][2] *= al1; oacc[n][3] *= al1;
        }

        uint32_t pah[4][4], pal[4][4];
#pragma unroll
        for (int j2 = 0; j2 < 4; ++j2) {
            float p00 = sacc[2 * j2][0],     p01 = sacc[2 * j2][1];
            float p02 = sacc[2 * j2][2],     p03 = sacc[2 * j2][3];
            float p10 = sacc[2 * j2 + 1][0], p11 = sacc[2 * j2 + 1][1];
            float p12 = sacc[2 * j2 + 1][2], p13 = sacc[2 * j2 + 1][3];
            pah[j2][0] = pk2h(p00, p01);
            pah[j2][1] = pk2h(p02, p03);
            pah[j2][2] = pk2h(p10, p11);
            pah[j2][3] = pk2h(p12, p13);
            f16 hh;
            hh = __float2half_rn(p00); p00 -= __half2float(hh);
            hh = __float2half_rn(p01); p01 -= __half2float(hh);
            hh = __float2half_rn(p02); p02 -= __half2float(hh);
            hh = __float2half_rn(p03); p03 -= __half2float(hh);
            hh = __float2half_rn(p10); p10 -= __half2float(hh);
            hh = __float2half_rn(p11); p11 -= __half2float(hh);
            hh = __float2half_rn(p12); p12 -= __half2float(hh);
            hh = __float2half_rn(p13); p13 -= __half2float(hh);
            pal[j2][0] = pk2h(p00, p01);
            pal[j2][1] = pk2h(p02, p03);
            pal[j2][2] = pk2h(p10, p11);
            pal[j2][3] = pk2h(p12, p13);
        }

#pragma unroll
        for (int ntp = 0; ntp < 4; ++ntp) {
            const int nt0 = 2 * ntp, nt1 = 2 * ntp + 1;
#pragma unroll
            for (int j2 = 0; j2 < 4; ++j2) {
                uint32_t vh0[4], vh1[4];
                const uint32_t v0off = (uint32_t)(((nt0 * 16 + lrow) * VSTR + j2 * 16 + lkh) * 2);
                const uint32_t v1off = (uint32_t)(((nt1 * 16 + lrow) * VSTR + j2 * 16 + lkh) * 2);
                ldm_x4(vh0, uVH + v0off);
                ldm_x4(vh1, uVH + v1off);
                mma_f16(oacc[2 * nt0],     pah[j2], vh0[0], vh0[2]);
                mma_f16(oacc[2 * nt0 + 1], pah[j2], vh0[1], vh0[3]);
                mma_f16(oacc[2 * nt1],     pah[j2], vh1[0], vh1[2]);
                mma_f16(oacc[2 * nt1 + 1], pah[j2], vh1[1], vh1[3]);
                mma_f16(oacc[2 * nt0],     pal[j2], vh0[0], vh0[2]);
                mma_f16(oacc[2 * nt0 + 1], pal[j2], vh0[1], vh0[3]);
                mma_f16(oacc[2 * nt1],     pal[j2], vh1[0], vh1[2]);
                mma_f16(oacc[2 * nt1 + 1], pal[j2], vh1[1], vh1[3]);
            }
        }
    }

    // epilogue: normalize, single fp16 limb for the O-proj
    const float i0 = 1.0f / l0;
    const float i1 = 1.0f / l1;
    const size_t row0 = ((size_t)b * SEQ + r0g) * HID + h * HDIM;
    const size_t row1 = ((size_t)b * SEQ + r1g) * HID + h * HDIM;
#pragma unroll
    for (int n = 0; n < 16; ++n) {
        const int col = n * 8 + 2 * lam;
        *(uint32_t*)(attnH + row0 + col) = pk2h(oacc[n][0] * i0, oacc[n][1] * i0);
        *(uint32_t*)(attnH + row1 + col) = pk2h(oacc[n][2] * i1, oacc[n][3] * i1);
    }
}

// ---------------------------------------------------------------------------
extern "C" void kernel_launch(void* const* d_in, const int* in_sizes, int n_in,
                              void* d_out, int out_size)
{
    (void)in_sizes; (void)n_in; (void)out_size;
    const float* hidden = (const float*)d_in[0];
    const float* w_qkv  = (const float*)d_in[1];
    const float* w_o    = (const float*)d_in[2];
    const int*   pos    = (const int*)d_in[3];
    float* out = (float*)d_out;

    f16 *hidH, *hidL, *wqkvt, *wot, *attnH;
    f16 *QH, *QL, *KH, *VtH;
    float *ctab, *stab;
    cudaGetSymbolAddress((void**)&hidH,  g_hidH);
    cudaGetSymbolAddress((void**)&hidL,  g_hidL);
    cudaGetSymbolAddress((void**)&wqkvt, g_wqkvt);
    cudaGetSymbolAddress((void**)&wot,   g_wot);
    cudaGetSymbolAddress((void**)&ctab,  g_ctab);
    cudaGetSymbolAddress((void**)&stab,  g_stab);
    cudaGetSymbolAddress((void**)&QH,    g_QH);
    cudaGetSymbolAddress((void**)&QL,    g_QL);
    cudaGetSymbolAddress((void**)&KH,    g_KH);
    cudaGetSymbolAddress((void**)&VtH,   g_VtH);
    cudaGetSymbolAddress((void**)&attnH, g_attnH);

    // 0) preprocessing
    split_f32h<<<(TOKENS * HID) / 1024, 256>>>(hidden, hidH, hidL);
    transpose_f16<<<dim3(QKVN / 32, HID / 32), dim3(32, 8)>>>(w_qkv, wqkvt, HID, QKVN);
    transpose_f16<<<dim3(HID / 32, HID / 32), dim3(32, 8)>>>(w_o, wot, HID, HID);
    rope_tab<<<(TOKENS * 64) / 256, 256>>>(pos, ctab, stab);

    // 1) QKV projection fused with RoPE + head-split + V-transpose
    const int gsmem = NSTG * STG_BYTES;   // 98304 -> 2 CTAs/SM
    cudaFuncSetAttribute(gemm_qkv, cudaFuncAttributeMaxDynamicSharedMemorySize, gsmem);
    gemm_qkv<<<(TOKENS / 128) * (QKVN / 128), 256, gsmem>>>(
        hidH, hidL, wqkvt, ctab, stab, QH, QL, KH, VtH, HID, TOKENS / 128);

    // 2) tensor-core causal flash attention -> single-limb fp16 attn
    cudaFuncSetAttribute(flash_mma, cudaFuncAttributeMaxDynamicSharedMemorySize, ATT_SMEM);
    flash_mma<<<dim3(SEQ / 128, NHEAD, BATCH), 256, ATT_SMEM>>>(
        QH, QL, KH, VtH, attnH);

    // 3) output projection (single-term fp16)
    const int osmem = NSTG * STG1_BYTES;  // 65536 -> 2 CTAs/SM
    cudaFuncSetAttribute(gemm_oproj, cudaFuncAttributeMaxDynamicSharedMemorySize, osmem);
    gemm_oproj<<<(TOKENS / 128) * (HID / 128), 256, osmem>>>(
        attnH, wot, out, HID, HID, TOKENS / 128);
}

// round 16
// speedup vs baseline: 1.9480x; 1.4799x over previous
#include <cuda_runtime.h>
#include <cuda_bf16.h>
#include <cuda_fp16.h>
#include <math.h>
#include <stdint.h>

#define BATCH 2
#define SEQ   2048
#define HID   4096
#define NHEAD 32
#define HDIM  128
#define TOKENS (BATCH * SEQ)     // 4096
#define QKVN  (3 * HID)          // 12288
#define HEADS (BATCH * NHEAD)    // 64

typedef __half f16;

// ---------------- scratch (device globals; no allocation allowed) ----------
__device__ f16   g_hidH[(size_t)TOKENS * HID];
__device__ f16   g_wqkvt[(size_t)QKVN * HID];
__device__ f16   g_wot[(size_t)HID * HID];
__device__ float g_ctab[(size_t)TOKENS * 64];
__device__ float g_stab[(size_t)TOKENS * 64];
__device__ f16   g_QH[(size_t)HEADS * SEQ * HDIM];
__device__ f16   g_QL[(size_t)HEADS * SEQ * HDIM];
__device__ f16   g_KH[(size_t)HEADS * SEQ * HDIM];
__device__ f16   g_VtH[(size_t)HEADS * HDIM * SEQ];
__device__ f16   g_attnH[(size_t)TOKENS * HID];

// ======================= helpers ==================================
__device__ __forceinline__ uint32_t smem_u32_of(const void* p) {
    uint32_t a;
    asm("{ .reg .u64 t; cvta.to.shared.u64 t, %1; cvt.u32.u64 %0, t; }" : "=r"(a) : "l"(p));
    return a;
}
__device__ __forceinline__ void ldm_x4(uint32_t* r, uint32_t addr) {
    asm volatile("ldmatrix.sync.aligned.m8n8.x4.shared.b16 {%0,%1,%2,%3}, [%4];"
                 : "=r"(r[0]), "=r"(r[1]), "=r"(r[2]), "=r"(r[3]) : "r"(addr));
}
__device__ __forceinline__ void mma_f16(float* d, const uint32_t* a, uint32_t b0, uint32_t b1) {
    asm volatile(
        "mma.sync.aligned.m16n8k16.row.col.f32.f16.f16.f32 "
        "{%0,%1,%2,%3},{%4,%5,%6,%7},{%8,%9},{%0,%1,%2,%3};"
        : "+f"(d[0]), "+f"(d[1]), "+f"(d[2]), "+f"(d[3])
        : "r"(a[0]), "r"(a[1]), "r"(a[2]), "r"(a[3]), "r"(b0), "r"(b1));
}
__device__ __forceinline__ void hsplit(float x, f16& hi, f16& lo) {
    hi = __float2half_rn(x);
    lo = __float2half_rn(x - __half2float(hi));
}
__device__ __forceinline__ uint32_t pk2h(float a, float b) {
    __half2 t = __floats2half2_rn(a, b);
    return *(uint32_t*)&t;
}
__device__ __forceinline__ void cp16(uint32_t smem, const void* g) {
    asm volatile("cp.async.cg.shared.global [%0], [%1], 16;" :: "r"(smem), "l"(g) : "memory");
}
__device__ __forceinline__ void cp_commit() {
    asm volatile("cp.async.commit_group;" ::: "memory");
}
template <int N> __device__ __forceinline__ void cp_wait() {
    asm volatile("cp.async.wait_group %0;" :: "n"(N) : "memory");
}

// ============ single-term fp16 tensor-core GEMM =============================
// tile 128x128, KC=64, 256 thr, NSTG=2, 2 CTAs/SM, K-phase rotation.
// mode 0: fp32 C out.  mode 1: fused QKV epilogue (RoPE Q/K, transpose V).
#define KC  64
#define STG_ARR (128 * KC * 2)       // 16384 B
#define STG_BYTES (2 * STG_ARR)      // 32768 B (Ah, Bh)
#define NSTG 2
#define EPAD 129
#define EPI_BYTES (128 * EPAD * 4)   // 66048 B (fused epilogue scratch)

__global__ __launch_bounds__(256, 2) void gemm_f16(const f16* __restrict__ Ah,
                                                   const f16* __restrict__ Bh,
                                                   float* __restrict__ C,
                                                   const float* __restrict__ ctab,
                                                   const float* __restrict__ stab,
                                                   f16* __restrict__ QH, f16* __restrict__ QL,
                                                   f16* __restrict__ KH, f16* __restrict__ VtH,
                                                   int N, int K, int Mtiles, int mode)
{
    extern __shared__ char gsm[];
    const uint32_t sbase = smem_u32_of(gsm);

    const int tid = threadIdx.x;
    const int warp = tid >> 5, lane = tid & 31;
    const int wm = warp & 3;
    const int wn = warp >> 2;

    const int bx = blockIdx.x;
    const int group = bx / (Mtiles * 8);
    const int rr = bx % (Mtiles * 8);
    const int bm = rr % Mtiles;
    const int bn = group * 8 + rr / Mtiles;

    const f16* Aph = Ah + (size_t)bm * 128 * K;
    const f16* Bph = Bh + (size_t)bn * 128 * K;

    const int lrow = lane & 15;
    const int lc_half = lane >> 4;

    float acc[2][8][4];
#pragma unroll
    for (int t = 0; t < 2; ++t)
#pragma unroll
        for (int n = 0; n < 8; ++n)
#pragma unroll
            for (int i = 0; i < 4; ++i) acc[t][n][i] = 0.f;

    const int nc = K / KC;   // 64
    const int phase = (bx & 3) * (nc >> 2);

    auto issue = [&](int c, int st) {
        const int kc = c * KC;
        const uint32_t sb = sbase + st * STG_BYTES;
#pragma unroll
        for (int q = 0; q < 4; ++q) {
            const int i = tid + q * 256;
            const int row = i >> 3;
            const int chunk = i & 7;
            const int pchunk = chunk ^ (row & 7);
            const uint32_t doff = (uint32_t)(row * 128 + pchunk * 16);
            const size_t soff = (size_t)row * K + kc + chunk * 8;
            cp16(sb + doff, Aph + soff);
            cp16(sb + STG_ARR + doff, Bph + soff);
        }
    };

    issue(phase, 0); cp_commit();

    for (int cc = 0; cc < nc; ++cc) {
        cp_wait<0>();
        __syncthreads();
        if (cc + 1 < nc) {
            int cn = cc + 1 + phase;
            if (cn >= nc) cn -= nc;
            issue(cn, (cc + 1) & 1);
            cp_commit();
        }

        const int st = cc & 1;
        const uint32_t uAh = sbase + st * STG_BYTES;
        const uint32_t uBh = uAh + STG_ARR;

#pragma unroll
        for (int ks = 0; ks < 4; ++ks) {
            const int lc = ks * 2 + lc_half;
            uint32_t ah[2][4];
#pragma unroll
            for (int t = 0; t < 2; ++t) {
                const int ar = wm * 32 + t * 16 + lrow;
                const uint32_t aoff = (uint32_t)(ar * 128 + (lc ^ (ar & 7)) * 16);
                ldm_x4(ah[t], uAh + aoff);
            }
#pragma unroll
            for (int nt = 0; nt < 4; ++nt) {
                const int br = wn * 64 + nt * 16 + lrow;
                const uint32_t boff = (uint32_t)(br * 128 + (lc ^ (br & 7)) * 16);
                uint32_t bh[4];
                ldm_x4(bh, uBh + boff);
                mma_f16(acc[0][2 * nt],     ah[0], bh[0], bh[2]);
                mma_f16(acc[1][2 * nt],     ah[1], bh[0], bh[2]);
                mma_f16(acc[0][2 * nt + 1], ah[0], bh[1], bh[3]);
                mma_f16(acc[1][2 * nt + 1], ah[1], bh[1], bh[3]);
            }
        }
    }

    const int g = lane >> 2;
    const int tc2 = (lane & 3) << 1;

    if (mode == 0) {
#pragma unroll
        for (int t = 0; t < 2; ++t) {
            const int row0 = bm * 128 + wm * 32 + t * 16 + g;
#pragma unroll
            for (int n = 0; n < 8; ++n) {
                const int col = bn * 128 + wn * 64 + n * 8 + tc2;
                *(float2*)(C + (size_t)row0 * N + col) = make_float2(acc[t][n][0], acc[t][n][1]);
                *(float2*)(C + (size_t)(row0 + 8) * N + col) = make_float2(acc[t][n][2], acc[t][n][3]);
            }
        }
        return;
    }

    // -------- fused QKV epilogue (needs EPI_BYTES of smem) -------------------
    float* spad = (float*)gsm;
    __syncthreads();
#pragma unroll
    for (int t = 0; t < 2; ++t) {
        const int r0 = wm * 32 + t * 16 + g;
#pragma unroll
        for (int n = 0; n < 8; ++n) {
            const int col = wn * 64 + n * 8 + tc2;
            spad[r0 * EPAD + col]           = acc[t][n][0];
            spad[r0 * EPAD + col + 1]       = acc[t][n][1];
            spad[(r0 + 8) * EPAD + col]     = acc[t][n][2];
            spad[(r0 + 8) * EPAD + col + 1] = acc[t][n][3];
        }
    }
    __syncthreads();

    const int region = bn >> 5;      // 0:Q 1:K 2:V
    const int head = bn & 31;

    if (region == 0) {
#pragma unroll
        for (int q = 0; q < 32; ++q) {
            const int p = tid + q * 256;
            const int tok = p >> 6;
            const int i = p & 63;
            const int gtok = bm * 128 + tok;
            const float x1 = spad[tok * EPAD + i];
            const float x2 = spad[tok * EPAD + 64 + i];
            const float cv = ctab[(size_t)gtok * 64 + i];
            const float sv = stab[(size_t)gtok * 64 + i];
            const float r1 = x1 * cv - x2 * sv;
            const float r2 = x2 * cv + x1 * sv;
            const int bb = gtok >> 11;
            const int ss = gtok & 2047;
            const size_t ob = ((size_t)(bb * NHEAD + head) * SEQ + ss) * HDIM;
            f16 hh, ll;
            hsplit(r1, hh, ll); QH[ob + i] = hh;      QL[ob + i] = ll;
            hsplit(r2, hh, ll); QH[ob + 64 + i] = hh; QL[ob + 64 + i] = ll;
        }
    } else if (region == 1) {
#pragma unroll
        for (int q = 0; q < 32; ++q) {
            const int p = tid + q * 256;
            const int tok = p >> 6;
            const int i = p & 63;
            const int gtok = bm * 128 + tok;
            const float x1 = spad[tok * EPAD + i];
            const float x2 = spad[tok * EPAD + 64 + i];
            const float cv = ctab[(size_t)gtok * 64 + i];
            const float sv = stab[(size_t)gtok * 64 + i];
            const float r1 = x1 * cv - x2 * sv;
            const float r2 = x2 * cv + x1 * sv;
            const int bb = gtok >> 11;
            const int ss = gtok & 2047;
            const size_t ob = ((size_t)(bb * NHEAD + head) * SEQ + ss) * HDIM;
            KH[ob + i]      = __float2half_rn(r1);
            KH[ob + 64 + i] = __float2half_rn(r2);
        }
    } else {
#pragma unroll
        for (int q = 0; q < 64; ++q) {
            const int p = tid + q * 256;
            const int tok = p & 127;
            const int d = p >> 7;
            const int gtok = bm * 128 + tok;
            const float v = spad[tok * EPAD + d];
            const int bb = gtok >> 11;
            const int ss = gtok & 2047;
            const size_t od = ((size_t)(bb * NHEAD + head) * HDIM + d) * SEQ + ss;
            VtH[od] = __float2half_rn(v);
        }
    }
}

// ---------------- RoPE cos/sin table (fp64 reduce + fp32 trig) --------------
__global__ __launch_bounds__(256) void rope_tab(const int* __restrict__ pos,
                                                float* __restrict__ ct,
                                                float* __restrict__ st)
{
    const int idx = blockIdx.x * 256 + threadIdx.x;
    const int tok = idx >> 6;
    const int i = idx & 63;
    double inv = exp(-9.210340371976184 * ((double)(2 * i) / 128.0));
    double ang = (double)pos[tok] * inv;
    double r = remainder(ang, 6.283185307179586476925286766559);
    float rf = (float)r;
    ct[idx] = cosf(rf);
    st[idx] = sinf(rf);
}

// ---------------- elementwise fp32 -> fp16 cast ------------------------------
__global__ __launch_bounds__(256) void cast_f16(const float* __restrict__ in,
                                                f16* __restrict__ out)
{
    const size_t i4 = (size_t)blockIdx.x * 256 + threadIdx.x;
    float4 v = *(const float4*)(in + i4 * 4);
    f16 h[4];
    h[0] = __float2half_rn(v.x); h[1] = __float2half_rn(v.y);
    h[2] = __float2half_rn(v.z); h[3] = __float2half_rn(v.w);
    *(uint2*)(out + i4 * 4) = *(uint2*)h;
}

// ---------------- transpose + round to single fp16 --------------------------
__global__ __launch_bounds__(256) void transpose_f16(const float* __restrict__ in,
                                                     f16* __restrict__ out,
                                                     int R, int Cc)
{
    __shared__ float t[32][33];
    const int c = blockIdx.x * 32 + threadIdx.x;
    const int r0 = blockIdx.y * 32 + threadIdx.y;
#pragma unroll
    for (int i = 0; i < 4; ++i)
        t[threadIdx.y + i * 8][threadIdx.x] = in[(size_t)(r0 + i * 8) * Cc + c];
    __syncthreads();
    const int rc = blockIdx.y * 32 + threadIdx.x;
    const int c0 = blockIdx.x * 32 + threadIdx.y;
#pragma unroll
    for (int i = 0; i < 4; ++i)
        out[(size_t)(c0 + i * 8) * R + rc] = __float2half_rn(t[threadIdx.x][threadIdx.y + i * 8]);
}

// ---------------- tensor-core flash attention (causal, fp16 2-term) ---------
#define QSTR 136
#define VSTR 72
#define oQH 0
#define oQL (oQH + 128 * QSTR * 2)
#define oKH (oQL + 128 * QSTR * 2)
#define oVH (oKH + 2 * 64 * QSTR * 2)
#define ATT_SMEM (oVH + 2 * 128 * VSTR * 2)

__global__ __launch_bounds__(256, 1) void flash_mma(const f16* __restrict__ QHg,
                                                    const f16* __restrict__ QLg,
                                                    const f16* __restrict__ KHg,
                                                    const f16* __restrict__ VtHg,
                                                    f16* __restrict__ attnH)
{
    extern __shared__ char asm_buf[];
    const uint32_t sb = smem_u32_of(asm_buf);

    const int tid = threadIdx.x;
    const int warp = tid >> 5, lane = tid & 31;
    const int g = lane >> 2;
    const int lam = lane & 3;
    const int lrow = lane & 15;
    const int lkh = (lane >> 4) << 3;

    const int qt = (int)(gridDim.x - 1 - blockIdx.x);
    const int h = blockIdx.y;
    const int b = blockIdx.z;
    const int qb = qt * 128;
    const size_t hoff = (size_t)(b * NHEAD + h) * SEQ * HDIM;
    const size_t voff = (size_t)(b * NHEAD + h) * HDIM * SEQ;

#pragma unroll
    for (int j = 0; j < 8; ++j) {
        const int i = tid + j * 256;
        const int row = i >> 4;
        const int seg = (i & 15) << 3;
        const uint32_t doff = (uint32_t)(row * QSTR + seg) * 2;
        const size_t soff = hoff + (size_t)(qb + row) * HDIM + seg;
        cp16(sb + oQH + doff, QHg + soff);
        cp16(sb + oQL + doff, QLg + soff);
    }
    cp_commit();

    const int ktmax = 2 * qt + 1;

    auto issueKV = [&](int kt, int buf) {
        const int kb = kt * 64;
#pragma unroll
        for (int j = 0; j < 4; ++j) {
            const int i = tid + j * 256;
            const int krow = i >> 4;
            const int kseg = (i & 15) << 3;
            const uint32_t kdoff = (uint32_t)(krow * QSTR + kseg) * 2;
            const size_t ksoff = hoff + (size_t)(kb + krow) * HDIM + kseg;
            cp16(sb + oKH + buf * (64 * QSTR * 2) + kdoff, KHg + ksoff);
            const int vrow = i >> 3;
            const int vseg = (i & 7) << 3;
            const uint32_t vdoff = (uint32_t)(vrow * VSTR + vseg) * 2;
            const size_t vsoff = voff + (size_t)vrow * SEQ + kb + vseg;
            cp16(sb + oVH + buf * (128 * VSTR * 2) + vdoff, VtHg + vsoff);
        }
    };

    issueKV(0, 0);
    cp_commit();

    float oacc[16][4];
#pragma unroll
    for (int n = 0; n < 16; ++n)
#pragma unroll
        for (int i = 0; i < 4; ++i) oacc[n][i] = 0.f;
    float m0 = -1e30f, m1 = -1e30f, l0 = 0.f, l1 = 0.f;
    const float scale2 = 0.1275174324f;   // (1/sqrt(128)) * log2(e)

    const int r0g = qb + warp * 16 + g;
    const int r1g = r0g + 8;

    for (int kt = 0; kt <= ktmax; ++kt) {
        const int kb = kt * 64;
        const int buf = kt & 1;

        cp_wait<0>();
        __syncthreads();
        if (kt < ktmax) { issueKV(kt + 1, buf ^ 1); cp_commit(); }

        const uint32_t uQH = sb + oQH, uQL = sb + oQL;
        const uint32_t uKH = sb + oKH + buf * (64 * QSTR * 2);
        const uint32_t uVH = sb + oVH + buf * (128 * VSTR * 2);

        float sacc[8][4];
#pragma unroll
        for (int n = 0; n < 8; ++n)
#pragma unroll
            for (int i = 0; i < 4; ++i) sacc[n][i] = 0.f;

#pragma unroll
        for (int ks = 0; ks < 8; ++ks) {
            uint32_t qh[4], ql[4];
            const uint32_t aoff = (uint32_t)(((warp * 16 + lrow) * QSTR + ks * 16 + lkh) * 2);
            ldm_x4(qh, uQH + aoff);
            ldm_x4(ql, uQL + aoff);
#pragma unroll
            for (int ntp = 0; ntp < 2; ++ntp) {
                const int nt0 = 2 * ntp, nt1 = 2 * ntp + 1;
                uint32_t bh0[4], bh1[4];
                const uint32_t b0off = (uint32_t)(((nt0 * 16 + lrow) * QSTR + ks * 16 + lkh) * 2);
                const uint32_t b1off = (uint32_t)(((nt1 * 16 + lrow) * QSTR + ks * 16 + lkh) * 2);
                ldm_x4(bh0, uKH + b0off);
                ldm_x4(bh1, uKH + b1off);
                mma_f16(sacc[2 * nt0],     qh, bh0[0], bh0[2]);
                mma_f16(sacc[2 * nt0 + 1], qh, bh0[1], bh0[3]);
                mma_f16(sacc[2 * nt1],     qh, bh1[0], bh1[2]);
                mma_f16(sacc[2 * nt1 + 1], qh, bh1[1], bh1[3]);
                mma_f16(sacc[2 * nt0],     ql, bh0[0], bh0[2]);
                mma_f16(sacc[2 * nt0 + 1], ql, bh0[1], bh0[3]);
                mma_f16(sacc[2 * nt1],     ql, bh1[0], bh1[2]);
                mma_f16(sacc[2 * nt1 + 1], ql, bh1[1], bh1[3]);
            }
        }

        const bool need_mask = (kt >= 2 * qt);
        float rm0 = -1e30f, rm1 = -1e30f;
#pragma unroll
        for (int j = 0; j < 8; ++j) {
            const int cg0 = kb + j * 8 + 2 * lam;
#pragma unroll
            for (int i = 0; i < 4; ++i) {
                float v = sacc[j][i] * scale2;
                if (need_mask) {
                    const int cg = cg0 + (i & 1);
                    const int rg = (i < 2) ? r0g : r1g;
                    if (cg > rg) v = -1e30f;
                }
                sacc[j][i] = v;
            }
            rm0 = fmaxf(rm0, fmaxf(sacc[j][0], sacc[j][1]));
            rm1 = fmaxf(rm1, fmaxf(sacc[j][2], sacc[j][3]));
        }
#pragma unroll
        for (int off = 1; off <= 2; off <<= 1) {
            rm0 = fmaxf(rm0, __shfl_xor_sync(0xffffffffu, rm0, off));
            rm1 = fmaxf(rm1, __shfl_xor_sync(0xffffffffu, rm1, off));
        }
        const float mn0 = fmaxf(m0, rm0);
        const float mn1 = fmaxf(m1, rm1);
        const float al0 = exp2f(m0 - mn0);
        const float al1 = exp2f(m1 - mn1);
        m0 = mn0; m1 = mn1;

        float rs0 = 0.f, rs1 = 0.f;
#pragma unroll
        for (int j = 0; j < 8; ++j) {
            sacc[j][0] = exp2f(sacc[j][0] - mn0);
            sacc[j][1] = exp2f(sacc[j][1] - mn0);
            sacc[j][2] = exp2f(sacc[j][2] - mn1);
            sacc[j][3] = exp2f(sacc[j][3] - mn1);
            rs0 += sacc[j][0] + sacc[j][1];
            rs1 += sacc[j][2] + sacc[j][3];
        }
#pragma unroll
        for (int off = 1; off <= 2; off <<= 1) {
            rs0 += __shfl_xor_sync(0xffffffffu, rs0, off);
            rs1 += __shfl_xor_sync(0xffffffffu, rs1, off);
        }
        l0 = l0 * al0 + rs0;
        l1 = l1 * al1 + rs1;

#pragma unroll
        for (int n = 0; n < 16; ++n) {
            oacc[n][0] *= al0; oacc[n][1] *= al0;
            oacc[n][2] *= al1; oacc[n][3] *= al1;
        }

        uint32_t pah[4][4], pal[4][4];
#pragma unroll
        for (int j2 = 0; j2 < 4; ++j2) {
            float p00 = sacc[2 * j2][0],     p01 = sacc[2 * j2][1];
            float p02 = sacc[2 * j2][2],     p03 = sacc[2 * j2][3];
            float p10 = sacc[2 * j2 + 1][0], p11 = sacc[2 * j2 + 1][1];
            float p12 = sacc[2 * j2 + 1][2], p13 = sacc[2 * j2 + 1][3];
            pah[j2][0] = pk2h(p00, p01);
            pah[j2][1] = pk2h(p02, p03);
            pah[j2][2] = pk2h(p10, p11);
            pah[j2][3] = pk2h(p12, p13);
            f16 hh;
            hh = __float2half_rn(p00); p00 -= __half2float(hh);
            hh = __float2half_rn(p01); p01 -= __half2float(hh);
            hh = __float2half_rn(p02); p02 -= __half2float(hh);
            hh = __float2half_rn(p03); p03 -= __half2float(hh);
            hh = __float2half_rn(p10); p10 -= __half2float(hh);
            hh = __float2half_rn(p11); p11 -= __half2float(hh);
            hh = __float2half_rn(p12); p12 -= __half2float(hh);
            hh = __float2half_rn(p13); p13 -= __half2float(hh);
            pal[j2][0] = pk2h(p00, p01);
            pal[j2][1] = pk2h(p02, p03);
            pal[j2][2] = pk2h(p10, p11);
            pal[j2][3] = pk2h(p12, p13);
        }

#pragma unroll
        for (int ntp = 0; ntp < 4; ++ntp) {
            const int nt0 = 2 * ntp, nt1 = 2 * ntp + 1;
#pragma unroll
            for (int j2 = 0; j2 < 4; ++j2) {
                uint32_t vh0[4], vh1[4];
                const uint32_t v0off = (uint32_t)(((nt0 * 16 + lrow) * VSTR + j2 * 16 + lkh) * 2);
                const uint32_t v1off = (uint32_t)(((nt1 * 16 + lrow) * VSTR + j2 * 16 + lkh) * 2);
                ldm_x4(vh0, uVH + v0off);
                ldm_x4(vh1, uVH + v1off);
                mma_f16(oacc[2 * nt0],     pah[j2], vh0[0], vh0[2]);
                mma_f16(oacc[2 * nt0 + 1], pah[j2], vh0[1], vh0[3]);
                mma_f16(oacc[2 * nt1],     pah[j2], vh1[0], vh1[2]);
                mma_f16(oacc[2 * nt1 + 1], pah[j2], vh1[1], vh1[3]);
                mma_f16(oacc[2 * nt0],     pal[j2], vh0[0], vh0[2]);
                mma_f16(oacc[2 * nt0 + 1], pal[j2], vh0[1], vh0[3]);
                mma_f16(oacc[2 * nt1],     pal[j2], vh1[0], vh1[2]);
                mma_f16(oacc[2 * nt1 + 1], pal[j2], vh1[1], vh1[3]);
            }
        }
    }

    // epilogue: normalize, single fp16 limb for the O-proj
    const float i0 = 1.0f / l0;
    const float i1 = 1.0f / l1;
    const size_t row0 = ((size_t)b * SEQ + r0g) * HID + h * HDIM;
    const size_t row1 = ((size_t)b * SEQ + r1g) * HID + h * HDIM;
#pragma unroll
    for (int n = 0; n < 16; ++n) {
        const int col = n * 8 + 2 * lam;
        *(uint32_t*)(attnH + row0 + col) = pk2h(oacc[n][0] * i0, oacc[n][1] * i0);
        *(uint32_t*)(attnH + row1 + col) = pk2h(oacc[n][2] * i1, oacc[n][3] * i1);
    }
}

// ---------------------------------------------------------------------------
extern "C" void kernel_launch(void* const* d_in, const int* in_sizes, int n_in,
                              void* d_out, int out_size)
{
    (void)in_sizes; (void)n_in; (void)out_size;
    const float* hidden = (const float*)d_in[0];
    const float* w_qkv  = (const float*)d_in[1];
    const float* w_o    = (const float*)d_in[2];
    const int*   pos    = (const int*)d_in[3];
    float* out = (float*)d_out;

    f16 *hidH, *wqkvt, *wot, *attnH;
    f16 *QH, *QL, *KH, *VtH;
    float *ctab, *stab;
    cudaGetSymbolAddress((void**)&hidH,  g_hidH);
    cudaGetSymbolAddress((void**)&wqkvt, g_wqkvt);
    cudaGetSymbolAddress((void**)&wot,   g_wot);
    cudaGetSymbolAddress((void**)&ctab,  g_ctab);
    cudaGetSymbolAddress((void**)&stab,  g_stab);
    cudaGetSymbolAddress((void**)&QH,    g_QH);
    cudaGetSymbolAddress((void**)&QL,    g_QL);
    cudaGetSymbolAddress((void**)&KH,    g_KH);
    cudaGetSymbolAddress((void**)&VtH,   g_VtH);
    cudaGetSymbolAddress((void**)&attnH, g_attnH);

    // 0) preprocessing
    cast_f16<<<(TOKENS * HID) / 1024, 256>>>(hidden, hidH);
    transpose_f16<<<dim3(QKVN / 32, HID / 32), dim3(32, 8)>>>(w_qkv, wqkvt, HID, QKVN);
    transpose_f16<<<dim3(HID / 32, HID / 32), dim3(32, 8)>>>(w_o, wot, HID, HID);
    rope_tab<<<(TOKENS * 64) / 256, 256>>>(pos, ctab, stab);

    // smem: pipeline needs NSTG*STG_BYTES (65536); fused epilogue needs EPI_BYTES (66048)
    const int qkv_smem = (EPI_BYTES > NSTG * STG_BYTES) ? EPI_BYTES : NSTG * STG_BYTES;
    cudaFuncSetAttribute(gemm_f16, cudaFuncAttributeMaxDynamicSharedMemorySize, qkv_smem);

    // 1) QKV projection (single-term fp16) + fused RoPE/head-split/V-transpose
    gemm_f16<<<(TOKENS / 128) * (QKVN / 128), 256, qkv_smem>>>(
        hidH, wqkvt, nullptr, ctab, stab, QH, QL, KH, VtH, QKVN, HID, TOKENS / 128, 1);

    // 2) tensor-core causal flash attention -> single-limb fp16 attn
    cudaFuncSetAttribute(flash_mma, cudaFuncAttributeMaxDynamicSharedMemorySize, ATT_SMEM);
    flash_mma<<<dim3(SEQ / 128, NHEAD, BATCH), 256, ATT_SMEM>>>(
        QH, QL, KH, VtH, attnH);

    // 3) output projection (single-term fp16; pipeline smem is enough)
    gemm_f16<<<(TOKENS / 128) * (HID / 128), 256, qkv_smem>>>(
        attnH, wot, out, nullptr, nullptr,
        nullptr, nullptr, nullptr, nullptr,
        HID, HID, TOKENS / 128, 0);
}